// round 12
// baseline (speedup 1.0000x reference)
#include <cuda_runtime.h>
#include <cuda_fp16.h>
#include <math.h>
#include <stdint.h>

#define D_    768
#define P_    2048
#define B_    4
#define H_    12
#define DFF_  3072
#define NTOK  (B_ * P_)      /* 8192 */
#define D3_   (3 * D_)       /* 2304 */
#define EPS_  1e-3f
#define SURV_ 0.9f

// ---------------- scratch (static device globals) ---------------------------
__device__ __half g_h   [NTOK * D_];     // LN output, fp16
__device__ __half g_qkvh[NTOK * D3_];    // fp16 QKV
__device__ float  g_x1  [NTOK * D_];
__device__ __half g_ffn [NTOK * DFF_];   // MLP hidden, fp16
// transposed weights: [N, K] layout, fp16
__device__ __half g_wq[D3_ * D_];
__device__ __half g_w1[DFF_ * D_];
__device__ __half g_w2[D_ * DFF_];

// ---------------- helpers ----------------------------------------------------
__device__ __forceinline__ uint32_t smem_u32(const void* p) {
    uint32_t a;
    asm("{ .reg .u64 t; cvta.to.shared.u64 t, %1; cvt.u32.u64 %0, t; }"
        : "=r"(a) : "l"(p));
    return a;
}
__device__ __forceinline__ void ldsm_x4(uint32_t* r, uint32_t addr) {
    asm volatile("ldmatrix.sync.aligned.m8n8.x4.shared.b16 {%0,%1,%2,%3}, [%4];"
                 : "=r"(r[0]), "=r"(r[1]), "=r"(r[2]), "=r"(r[3]) : "r"(addr));
}
__device__ __forceinline__ void ldsm_x4_t(uint32_t* r, uint32_t addr) {
    asm volatile("ldmatrix.sync.aligned.m8n8.x4.trans.shared.b16 {%0,%1,%2,%3}, [%4];"
                 : "=r"(r[0]), "=r"(r[1]), "=r"(r[2]), "=r"(r[3]) : "r"(addr));
}
__device__ __forceinline__ void mma16816(float* c, const uint32_t* a,
                                         uint32_t b0, uint32_t b1) {
    asm volatile(
        "mma.sync.aligned.m16n8k16.row.col.f32.f16.f16.f32 "
        "{%0,%1,%2,%3}, {%4,%5,%6,%7}, {%8,%9}, {%0,%1,%2,%3};"
        : "+f"(c[0]), "+f"(c[1]), "+f"(c[2]), "+f"(c[3])
        : "r"(a[0]), "r"(a[1]), "r"(a[2]), "r"(a[3]), "r"(b0), "r"(b1));
}
__device__ __forceinline__ float ex2f(float x) {
    float y; asm("ex2.approx.f32 %0, %1;" : "=f"(y) : "f"(x)); return y;
}
__device__ __forceinline__ uint32_t h2ex2(uint32_t a) {
    uint32_t d; asm("ex2.approx.f16x2 %0, %1;" : "=r"(d) : "r"(a)); return d;
}
// packed fp16x2 = {lo half: first arg, hi half: second arg}
__device__ __forceinline__ uint32_t pack_f16x2(float lo, float hi) {
    uint32_t d;
    asm("cvt.rn.f16x2.f32 %0, %1, %2;" : "=r"(d) : "f"(hi), "f"(lo));
    return d;
}
__device__ __forceinline__ float2 h2f2(uint32_t p) {
    __half2 h = *(__half2*)&p;
    return __half22float2(h);
}
__device__ __forceinline__ void cp_async16(uint32_t dst, const void* src) {
    asm volatile("cp.async.cg.shared.global [%0], [%1], 16;"
                 :: "r"(dst), "l"(src));
}
#define CP_COMMIT() asm volatile("cp.async.commit_group;" ::: "memory")
#define CP_WAIT(n)  asm volatile("cp.async.wait_group %0;" :: "n"(n) : "memory")

// ---------------- LayerNorm -> fp16 (warp-per-row) ---------------------------
__global__ void __launch_bounds__(256) ln_f16_kernel(
    const float* __restrict__ x, const float* __restrict__ g,
    const float* __restrict__ b, __half* __restrict__ out)
{
    const int row  = blockIdx.x * 8 + (threadIdx.x >> 5);
    const int lane = threadIdx.x & 31;
    const float4* xr = (const float4*)(x + (size_t)row * D_);
    const float4* gv = (const float4*)g;
    const float4* bv = (const float4*)b;

    float4 v[6];
    float s = 0.f;
    #pragma unroll
    for (int k = 0; k < 6; k++) {
        v[k] = xr[lane + 32 * k];
        s += v[k].x + v[k].y + v[k].z + v[k].w;
    }
    #pragma unroll
    for (int o = 16; o; o >>= 1) s += __shfl_xor_sync(0xffffffffu, s, o);
    const float mu = s * (1.0f / D_);

    float q = 0.f;
    #pragma unroll
    for (int k = 0; k < 6; k++) {
        v[k].x -= mu; v[k].y -= mu; v[k].z -= mu; v[k].w -= mu;
        q += v[k].x * v[k].x + v[k].y * v[k].y + v[k].z * v[k].z + v[k].w * v[k].w;
    }
    #pragma unroll
    for (int o = 16; o; o >>= 1) q += __shfl_xor_sync(0xffffffffu, q, o);
    const float rs = rsqrtf(q * (1.0f / D_) + EPS_);

    uint2* hp = (uint2*)(out + (size_t)row * D_);
    #pragma unroll
    for (int k = 0; k < 6; k++) {
        const int i4 = lane + 32 * k;
        float4 gg = gv[i4], bb = bv[i4];
        float o0 = v[k].x * rs * gg.x + bb.x;
        float o1 = v[k].y * rs * gg.y + bb.y;
        float o2 = v[k].z * rs * gg.z + bb.z;
        float o3 = v[k].w * rs * gg.w + bb.w;
        hp[i4] = make_uint2(pack_f16x2(o0, o1), pack_f16x2(o2, o3));
    }
}

// ---------------- weight transpose + cast: w[K,N] -> wt[N,K] fp16 -----------
__global__ void __launch_bounds__(256) wcast_kernel(
    const float* __restrict__ w, __half* __restrict__ wt, int K, int N)
{
    __shared__ float t[32][33];
    const int n0 = blockIdx.x * 32, k0 = blockIdx.y * 32;
    const int tx = threadIdx.x & 31, ty = threadIdx.x >> 5;
    #pragma unroll
    for (int j = 0; j < 4; j++) {
        int k = ty + j * 8;
        t[k][tx] = w[(size_t)(k0 + k) * N + n0 + tx];
    }
    __syncthreads();
    #pragma unroll
    for (int j = 0; j < 4; j++) {
        int n = ty + j * 8;
        wt[(size_t)(n0 + n) * K + k0 + tx] = __float2half(t[tx][n]);
    }
}

// ---------------- MMA GEMM: C[M,N] = A[M,K] @ B[N,K]^T, fp16 single-pass ----
// 128x128 tile, K chunk 64, 256 threads, 8 warps (4m x 2n), warp 32x64.
// cp.async 2-stage, 2 CTAs/SM.
// EPI: 1 bias+GELU->fp16 ; 3 bias->fp16
#define BM   128
#define BN   128
#define BKC  64
#define ROWB 144          /* 64 fp16 = 128B + 16B pad */
#define TILEB (128 * ROWB)     /* 18432 */
#define STAGEB (2 * TILEB)     /* 36864 */
#define GEMM_SMEM (2 * STAGEB) /* 73728 */

template <int EPI>
__global__ void __launch_bounds__(256, 2) gemm_mma(
    const __half* __restrict__ A_g, const __half* __restrict__ B_g,
    const float* __restrict__ bias,
    __half* __restrict__ Ch, int M, int N, int K)
{
    extern __shared__ char dsm[];
    const uint32_t sbase = smem_u32(dsm);

    const int tid  = threadIdx.x;
    const int lane = tid & 31;
    const int wid  = tid >> 5;
    const int wm   = wid & 3;
    const int wn   = wid >> 2;
    const int m0   = blockIdx.y * BM;
    const int n0   = blockIdx.x * BN;

    const int a_row = lane & 15;
    const int a_col = (lane >> 4) << 3;
    const uint32_t offA = (uint32_t)((wm * 32 + a_row) * ROWB + a_col * 2);
    const int b_row = (lane & 7) | ((lane >> 4) << 3);
    const int b_col = ((lane >> 3) & 1) << 3;
    const uint32_t offB = (uint32_t)(TILEB + (wn * 64 + b_row) * ROWB + b_col * 2);

    float acc[2][8][4];
    #pragma unroll
    for (int i = 0; i < 2; i++)
        #pragma unroll
        for (int j = 0; j < 8; j++)
            #pragma unroll
            for (int k = 0; k < 4; k++) acc[i][j][k] = 0.f;

    const int ldu = K >> 3;
    const uint4* ga = (const uint4*)A_g;
    const uint4* gb = (const uint4*)B_g;

    const int nchunks = K / BKC;

    auto issue = [&](int stage, int ch) {
        const int k0u = ch * (BKC / 8);
        const uint32_t so = sbase + (uint32_t)stage * STAGEB;
        #pragma unroll
        for (int i = 0; i < 4; i++) {
            const int idx = tid + i * 256;
            const int r = idx >> 3, q = idx & 7;
            const uint32_t d = so + (uint32_t)(r * ROWB + q * 16);
            cp_async16(d,         ga + (size_t)(m0 + r) * ldu + k0u + q);
            cp_async16(d + TILEB, gb + (size_t)(n0 + r) * ldu + k0u + q);
        }
    };

    issue(0, 0);
    CP_COMMIT();

    for (int ch = 0; ch < nchunks; ch++) {
        if (ch + 1 < nchunks) {
            issue((ch + 1) & 1, ch + 1);
            CP_COMMIT();
            CP_WAIT(1);
        } else {
            CP_WAIT(0);
        }
        __syncthreads();

        const uint32_t st = sbase + (uint32_t)(ch & 1) * STAGEB;
        const uint32_t aT = st + offA;
        const uint32_t bT = st + offB;

        #pragma unroll
        for (int ks = 0; ks < BKC; ks += 16) {
            uint32_t ah[2][4];
            #pragma unroll
            for (int mt = 0; mt < 2; mt++)
                ldsm_x4(ah[mt], aT + mt * (16 * ROWB) + ks * 2);
            #pragma unroll
            for (int np = 0; np < 4; np++) {
                uint32_t bh[4];
                ldsm_x4(bh, bT + np * (16 * ROWB) + ks * 2);
                #pragma unroll
                for (int mt = 0; mt < 2; mt++) {
                    mma16816(acc[mt][2 * np],     ah[mt], bh[0], bh[1]);
                    mma16816(acc[mt][2 * np + 1], ah[mt], bh[2], bh[3]);
                }
            }
        }
        __syncthreads();
    }

    // epilogue
    const int lr = lane >> 2;
    const int lc = (lane & 3) * 2;
    #pragma unroll
    for (int mt = 0; mt < 2; mt++) {
        #pragma unroll
        for (int nt = 0; nt < 8; nt++) {
            #pragma unroll
            for (int hh = 0; hh < 2; hh++) {
                const int gr = m0 + wm * 32 + mt * 16 + lr + hh * 8;
                const int gc = n0 + wn * 64 + nt * 8 + lc;
                float v0 = acc[mt][nt][hh * 2 + 0] + bias[gc];
                float v1 = acc[mt][nt][hh * 2 + 1] + bias[gc + 1];
                const size_t go = (size_t)gr * N + gc;
                if (EPI == 1) {
                    v0 = 0.5f * v0 * (1.0f + erff(v0 * 0.70710678118654752f));
                    v1 = 0.5f * v1 * (1.0f + erff(v1 * 0.70710678118654752f));
                }
                ((uint32_t*)Ch)[go >> 1] = pack_f16x2(v0, v1);
            }
        }
    }
}

// ---------------- MMA GEMM 128x64 tile (MLP2, EPI2: bias,*0.9,+res->fp32) ---
// 256 threads, 8 warps (4m x 2n), warp 32x32. 768 CTAs -> no 1.3-wave tail.
#define N64_TA (128 * ROWB)        /* 18432 */
#define N64_TB (64 * ROWB)         /* 9216  */
#define N64_STAGE (N64_TA + N64_TB)
#define N64_SMEM (2 * N64_STAGE)   /* 55296 */

__global__ void __launch_bounds__(256, 3) gemm_mma_n64(
    const __half* __restrict__ A_g, const __half* __restrict__ B_g,
    const float* __restrict__ bias, const float* __restrict__ res,
    float* __restrict__ Cf, int M, int N, int K)
{
    extern __shared__ char dsm[];
    const uint32_t sbase = smem_u32(dsm);

    const int tid  = threadIdx.x;
    const int lane = tid & 31;
    const int wid  = tid >> 5;
    const int wm   = wid & 3;
    const int wn   = wid >> 2;
    const int m0   = blockIdx.y * BM;
    const int n0   = blockIdx.x * 64;

    const int a_row = lane & 15;
    const int a_col = (lane >> 4) << 3;
    const uint32_t offA = (uint32_t)((wm * 32 + a_row) * ROWB + a_col * 2);
    const int b_row = (lane & 7) | ((lane >> 4) << 3);
    const int b_col = ((lane >> 3) & 1) << 3;
    const uint32_t offB = (uint32_t)(N64_TA + (wn * 32 + b_row) * ROWB + b_col * 2);

    float acc[2][4][4];
    #pragma unroll
    for (int i = 0; i < 2; i++)
        #pragma unroll
        for (int j = 0; j < 4; j++)
            #pragma unroll
            for (int k = 0; k < 4; k++) acc[i][j][k] = 0.f;

    const int ldu = K >> 3;
    const uint4* ga = (const uint4*)A_g;
    const uint4* gb = (const uint4*)B_g;

    const int nchunks = K / BKC;

    auto issue = [&](int stage, int ch) {
        const int k0u = ch * (BKC / 8);
        const uint32_t so = sbase + (uint32_t)stage * N64_STAGE;
        #pragma unroll
        for (int i = 0; i < 4; i++) {           // A: 1024 uint4
            const int idx = tid + i * 256;
            const int r = idx >> 3, q = idx & 7;
            cp_async16(so + (uint32_t)(r * ROWB + q * 16),
                       ga + (size_t)(m0 + r) * ldu + k0u + q);
        }
        #pragma unroll
        for (int i = 0; i < 2; i++) {           // B: 512 uint4
            const int idx = tid + i * 256;
            const int r = idx >> 3, q = idx & 7;
            cp_async16(so + N64_TA + (uint32_t)(r * ROWB + q * 16),
                       gb + (size_t)(n0 + r) * ldu + k0u + q);
        }
    };

    issue(0, 0);
    CP_COMMIT();

    for (int ch = 0; ch < nchunks; ch++) {
        if (ch + 1 < nchunks) {
            issue((ch + 1) & 1, ch + 1);
            CP_COMMIT();
            CP_WAIT(1);
        } else {
            CP_WAIT(0);
        }
        __syncthreads();

        const uint32_t st = sbase + (uint32_t)(ch & 1) * N64_STAGE;
        const uint32_t aT = st + offA;
        const uint32_t bT = st + offB;

        #pragma unroll
        for (int ks = 0; ks < BKC; ks += 16) {
            uint32_t ah[2][4];
            #pragma unroll
            for (int mt = 0; mt < 2; mt++)
                ldsm_x4(ah[mt], aT + mt * (16 * ROWB) + ks * 2);
            uint32_t bh[2][4];
            #pragma unroll
            for (int np = 0; np < 2; np++)
                ldsm_x4(bh[np], bT + np * (16 * ROWB) + ks * 2);
            #pragma unroll
            for (int mt = 0; mt < 2; mt++)
                #pragma unroll
                for (int np = 0; np < 2; np++) {
                    mma16816(acc[mt][2 * np],     ah[mt], bh[np][0], bh[np][1]);
                    mma16816(acc[mt][2 * np + 1], ah[mt], bh[np][2], bh[np][3]);
                }
        }
        __syncthreads();
    }

    const int lr = lane >> 2;
    const int lc = (lane & 3) * 2;
    #pragma unroll
    for (int mt = 0; mt < 2; mt++) {
        #pragma unroll
        for (int nt = 0; nt < 4; nt++) {
            #pragma unroll
            for (int hh = 0; hh < 2; hh++) {
                const int gr = m0 + wm * 32 + mt * 16 + lr + hh * 8;
                const int gc = n0 + wn * 32 + nt * 8 + lc;
                float v0 = acc[mt][nt][hh * 2 + 0] + bias[gc];
                float v1 = acc[mt][nt][hh * 2 + 1] + bias[gc + 1];
                const size_t go = (size_t)gr * N + gc;
                float2 rr = *(const float2*)&res[go];
                float2 o2 = make_float2(v0 * SURV_ + rr.x, v1 * SURV_ + rr.y);
                *(float2*)&Cf[go] = o2;
            }
        }
    }
}

// ---------------- Flash attention v3 (row-sums on FMA pipe) ------------------
#define FQT 64
#define KT  64
#define QB_  9216                  /* 64 rows * 144B */
#define KB_  9216
#define FLASH_SMEM (QB_ + 4 * KB_) /* 46080 */

__global__ void __launch_bounds__(128) flash_mma(
    const __half* __restrict__ qkv, const float* __restrict__ x,
    float* __restrict__ x1)
{
    extern __shared__ char fsm[];
    const uint32_t sb = smem_u32(fsm);

    const int t = threadIdx.x;
    const int lane = t & 31, wid = t >> 5;
    const int qt = blockIdx.x, h = blockIdx.y, b = blockIdx.z;
    const size_t base = (size_t)b * P_ * D3_;
    const int q0 = qt * FQT, hc = h * 64;

    #pragma unroll
    for (int i = 0; i < 4; i++) {
        int idx = t + i * 128;
        int r = idx >> 3, c8 = (idx & 7) << 3;
        *(uint4*)(fsm + r * 144 + c8 * 2) =
            *(const uint4*)(qkv + base + (size_t)(q0 + r) * D3_ + hc + c8);
    }

    auto issueKV = [&](int stage, int kt) {
        const int k0 = kt * KT;
        const uint32_t kb = sb + QB_ + (uint32_t)stage * KB_;
        const uint32_t vb = sb + QB_ + 2 * KB_ + (uint32_t)stage * KB_;
        #pragma unroll
        for (int i = 0; i < 4; i++) {
            int idx = t + i * 128;
            int r = idx >> 3, c8 = (idx & 7) << 3;
            cp_async16(kb + r * 144 + c8 * 2,
                       qkv + base + (size_t)(k0 + r) * D3_ + D_ + hc + c8);
            cp_async16(vb + r * 144 + c8 * 2,
                       qkv + base + (size_t)(k0 + r) * D3_ + 2 * D_ + hc + c8);
        }
    };

    issueKV(0, 0);
    CP_COMMIT();
    __syncthreads();

    uint32_t qf[4][4];
    {
        const int qr = lane & 15;
        const int qc = (lane >> 4) << 3;
        #pragma unroll
        for (int ks = 0; ks < 4; ks++)
            ldsm_x4(qf[ks], sb + (wid * 16 + qr) * 144 + (ks * 16 + qc) * 2);
    }

    float mrow[2] = {-1e30f, -1e30f};
    float lrow[2] = {0.f, 0.f};
    float o[8][4];
    #pragma unroll
    for (int i = 0; i < 8; i++)
        #pragma unroll
        for (int j = 0; j < 4; j++) o[i][j] = 0.f;

    const float SCL = 0.18033688011112042f;  // (1/8) * log2(e)

    const int krow = (lane & 7) + ((lane >> 4) << 3);
    const int kcol = ((lane >> 3) & 1) << 3;
    const int vrow = (lane & 7) + (((lane >> 3) & 1) << 3);
    const int vcol = (lane >> 4) << 3;

    const int niter = P_ / KT;
    for (int kt = 0; kt < niter; kt++) {
        if (kt + 1 < niter) {
            issueKV((kt + 1) & 1, kt + 1);
            CP_COMMIT();
            CP_WAIT(1);
        } else {
            CP_WAIT(0);
        }
        __syncthreads();

        const uint32_t kst = sb + QB_ + (uint32_t)(kt & 1) * KB_;
        const uint32_t vst = sb + QB_ + 2 * KB_ + (uint32_t)(kt & 1) * KB_;

        float s[8][4];
        #pragma unroll
        for (int i = 0; i < 8; i++)
            #pragma unroll
            for (int j = 0; j < 4; j++) s[i][j] = 0.f;
        #pragma unroll
        for (int ks = 0; ks < 4; ks++) {
            #pragma unroll
            for (int tp = 0; tp < 4; tp++) {
                uint32_t kf[4];
                ldsm_x4(kf, kst + (tp * 16 + krow) * 144 + (ks * 16 + kcol) * 2);
                mma16816(s[2 * tp],     qf[ks], kf[0], kf[1]);
                mma16816(s[2 * tp + 1], qf[ks], kf[2], kf[3]);
            }
        }

        float pm0 = -1e30f, pm1 = -1e30f;
        #pragma unroll
        for (int nt = 0; nt < 8; nt++) {
            pm0 = fmaxf(pm0, fmaxf(s[nt][0], s[nt][1]));
            pm1 = fmaxf(pm1, fmaxf(s[nt][2], s[nt][3]));
        }
        pm0 = fmaxf(pm0, __shfl_xor_sync(0xffffffffu, pm0, 1));
        pm0 = fmaxf(pm0, __shfl_xor_sync(0xffffffffu, pm0, 2));
        pm1 = fmaxf(pm1, __shfl_xor_sync(0xffffffffu, pm1, 1));
        pm1 = fmaxf(pm1, __shfl_xor_sync(0xffffffffu, pm1, 2));
        const float mn0 = fmaxf(mrow[0], pm0);
        const float mn1 = fmaxf(mrow[1], pm1);
        const float f0 = ex2f((mrow[0] - mn0) * SCL);
        const float f1 = ex2f((mrow[1] - mn1) * SCL);

        uint32_t pf[4][4];
        #pragma unroll
        for (int ks = 0; ks < 4; ks++) {
            pf[ks][0] = h2ex2(pack_f16x2((s[2 * ks][0] - mn0) * SCL,
                                         (s[2 * ks][1] - mn0) * SCL));
            pf[ks][1] = h2ex2(pack_f16x2((s[2 * ks][2] - mn1) * SCL,
                                         (s[2 * ks][3] - mn1) * SCL));
            pf[ks][2] = h2ex2(pack_f16x2((s[2 * ks + 1][0] - mn0) * SCL,
                                         (s[2 * ks + 1][1] - mn0) * SCL));
            pf[ks][3] = h2ex2(pack_f16x2((s[2 * ks + 1][2] - mn1) * SCL,
                                         (s[2 * ks + 1][3] - mn1) * SCL));
        }

        // row sums of fp16 P, accumulated exactly in fp32 on the FMA pipe
        float la0 = 0.f, la1 = 0.f;
        #pragma unroll
        for (int ks = 0; ks < 4; ks++) {
            float2 a = h2f2(pf[ks][0]), c = h2f2(pf[ks][2]);
            la0 += (a.x + a.y) + (c.x + c.y);
            float2 bq = h2f2(pf[ks][1]), d = h2f2(pf[ks][3]);
            la1 += (bq.x + bq.y) + (d.x + d.y);
        }
        la0 += __shfl_xor_sync(0xffffffffu, la0, 1);
        la0 += __shfl_xor_sync(0xffffffffu, la0, 2);
        la1 += __shfl_xor_sync(0xffffffffu, la1, 1);
        la1 += __shfl_xor_sync(0xffffffffu, la1, 2);

        lrow[0] = lrow[0] * f0 + la0;
        lrow[1] = lrow[1] * f1 + la1;
        mrow[0] = mn0;
        mrow[1] = mn1;

        #pragma unroll
        for (int nt = 0; nt < 8; nt++) {
            o[nt][0] *= f0; o[nt][1] *= f0;
            o[nt][2] *= f1; o[nt][3] *= f1;
        }

        #pragma unroll
        for (int ks = 0; ks < 4; ks++) {
            #pragma unroll
            for (int tp = 0; tp < 4; tp++) {
                uint32_t vf[4];
                ldsm_x4_t(vf, vst + (ks * 16 + vrow) * 144 + (tp * 16 + vcol) * 2);
                mma16816(o[2 * tp],     pf[ks], vf[0], vf[1]);
                mma16816(o[2 * tp + 1], pf[ks], vf[2], vf[3]);
            }
        }
        __syncthreads();
    }

    const float inv0 = 1.0f / lrow[0];
    const float inv1 = 1.0f / lrow[1];
    const int r0 = q0 + wid * 16 + (lane >> 2);
    const size_t row0 = ((size_t)b * P_ + r0) * D_ + hc + (lane & 3) * 2;
    const size_t row1 = row0 + 8 * D_;
    #pragma unroll
    for (int nt = 0; nt < 8; nt++) {
        float2 xa = *(const float2*)&x[row0 + nt * 8];
        float2 ra;
        ra.x = o[nt][0] * inv0 * SURV_ + xa.x;
        ra.y = o[nt][1] * inv0 * SURV_ + xa.y;
        *(float2*)&x1[row0 + nt * 8] = ra;
        float2 xb = *(const float2*)&x[row1 + nt * 8];
        float2 rb;
        rb.x = o[nt][2] * inv1 * SURV_ + xb.x;
        rb.y = o[nt][3] * inv1 * SURV_ + xb.y;
        *(float2*)&x1[row1 + nt * 8] = rb;
    }
}

// ---------------- launch ----------------------------------------------------
extern "C" void kernel_launch(void* const* d_in, const int* in_sizes, int n_in,
                              void* d_out, int out_size)
{
    const float* x     = (const float*)d_in[0];
    const float* ln1_g = (const float*)d_in[1];
    const float* ln1_b = (const float*)d_in[2];
    const float* w_qkv = (const float*)d_in[3];
    const float* b_qkv = (const float*)d_in[4];
    const float* ln2_g = (const float*)d_in[5];
    const float* ln2_b = (const float*)d_in[6];
    const float* w1    = (const float*)d_in[7];
    const float* b1    = (const float*)d_in[8];
    const float* w2    = (const float*)d_in[9];
    const float* b2    = (const float*)d_in[10];
    float* out = (float*)d_out;

    __half *h, *qkvh, *ffn, *wq, *w1t, *w2t;
    float *x1;
    cudaGetSymbolAddress((void**)&h,    g_h);
    cudaGetSymbolAddress((void**)&qkvh, g_qkvh);
    cudaGetSymbolAddress((void**)&x1,   g_x1);
    cudaGetSymbolAddress((void**)&ffn,  g_ffn);
    cudaGetSymbolAddress((void**)&wq,   g_wq);
    cudaGetSymbolAddress((void**)&w1t,  g_w1);
    cudaGetSymbolAddress((void**)&w2t,  g_w2);

    cudaFuncSetAttribute(gemm_mma<1>,
                         cudaFuncAttributeMaxDynamicSharedMemorySize, GEMM_SMEM);
    cudaFuncSetAttribute(gemm_mma<3>,
                         cudaFuncAttributeMaxDynamicSharedMemorySize, GEMM_SMEM);
    cudaFuncSetAttribute(gemm_mma_n64,
                         cudaFuncAttributeMaxDynamicSharedMemorySize, N64_SMEM);
    cudaFuncSetAttribute(flash_mma,
                         cudaFuncAttributeMaxDynamicSharedMemorySize, FLASH_SMEM);

    // weight transpose + cast
    wcast_kernel<<<dim3(D3_ / 32, D_ / 32), 256>>>(w_qkv, wq, D_, D3_);
    wcast_kernel<<<dim3(DFF_ / 32, D_ / 32), 256>>>(w1, w1t, D_, DFF_);
    wcast_kernel<<<dim3(D_ / 32, DFF_ / 32), 256>>>(w2, w2t, DFF_, D_);

    // 1) LN1 -> fp16
    ln_f16_kernel<<<NTOK / 8, 256>>>(x, ln1_g, ln1_b, h);
    // 2) QKV projection -> fp16
    gemm_mma<3><<<dim3(D3_ / BN, NTOK / BM), 256, GEMM_SMEM>>>(
        h, wq, b_qkv, qkvh, NTOK, D3_, D_);
    // 3) attention + residual -> x1
    flash_mma<<<dim3(P_ / FQT, H_, B_), 128, FLASH_SMEM>>>(qkvh, x, x1);
    // 4) LN2 -> fp16
    ln_f16_kernel<<<NTOK / 8, 256>>>(x1, ln2_g, ln2_b, h);
    // 5) MLP up + GELU -> fp16
    gemm_mma<1><<<dim3(DFF_ / BN, NTOK / BM), 256, GEMM_SMEM>>>(
        h, w1t, b1, ffn, NTOK, DFF_, D_);
    // 6) MLP down + droppath + residual -> out (128x64 tile, no wave tail)
    gemm_mma_n64<<<dim3(D_ / 64, NTOK / BM), 256, N64_SMEM>>>(
        ffn, w2t, b2, x1, out, NTOK, D_, DFF_);
}

// round 13
// speedup vs baseline: 1.0089x; 1.0089x over previous
#include <cuda_runtime.h>
#include <cuda_fp16.h>
#include <math.h>
#include <stdint.h>

#define D_    768
#define P_    2048
#define B_    4
#define H_    12
#define DFF_  3072
#define NTOK  (B_ * P_)      /* 8192 */
#define D3_   (3 * D_)       /* 2304 */
#define EPS_  1e-3f
#define SURV_ 0.9f

// ---------------- scratch (static device globals) ---------------------------
__device__ __half g_h   [NTOK * D_];     // LN output, fp16
__device__ __half g_qkvh[NTOK * D3_];    // fp16 QKV
__device__ float  g_x1  [NTOK * D_];
__device__ __half g_ffn [NTOK * DFF_];   // MLP hidden, fp16
__device__ float  g_part[2 * NTOK * D_]; // MLP2 split-K partials
// transposed weights: [N, K] layout, fp16
__device__ __half g_wq[D3_ * D_];
__device__ __half g_w1[DFF_ * D_];
__device__ __half g_w2[D_ * DFF_];

// ---------------- helpers ----------------------------------------------------
__device__ __forceinline__ uint32_t smem_u32(const void* p) {
    uint32_t a;
    asm("{ .reg .u64 t; cvta.to.shared.u64 t, %1; cvt.u32.u64 %0, t; }"
        : "=r"(a) : "l"(p));
    return a;
}
__device__ __forceinline__ void ldsm_x4(uint32_t* r, uint32_t addr) {
    asm volatile("ldmatrix.sync.aligned.m8n8.x4.shared.b16 {%0,%1,%2,%3}, [%4];"
                 : "=r"(r[0]), "=r"(r[1]), "=r"(r[2]), "=r"(r[3]) : "r"(addr));
}
__device__ __forceinline__ void ldsm_x4_t(uint32_t* r, uint32_t addr) {
    asm volatile("ldmatrix.sync.aligned.m8n8.x4.trans.shared.b16 {%0,%1,%2,%3}, [%4];"
                 : "=r"(r[0]), "=r"(r[1]), "=r"(r[2]), "=r"(r[3]) : "r"(addr));
}
__device__ __forceinline__ void mma16816(float* c, const uint32_t* a,
                                         uint32_t b0, uint32_t b1) {
    asm volatile(
        "mma.sync.aligned.m16n8k16.row.col.f32.f16.f16.f32 "
        "{%0,%1,%2,%3}, {%4,%5,%6,%7}, {%8,%9}, {%0,%1,%2,%3};"
        : "+f"(c[0]), "+f"(c[1]), "+f"(c[2]), "+f"(c[3])
        : "r"(a[0]), "r"(a[1]), "r"(a[2]), "r"(a[3]), "r"(b0), "r"(b1));
}
__device__ __forceinline__ float ex2f(float x) {
    float y; asm("ex2.approx.f32 %0, %1;" : "=f"(y) : "f"(x)); return y;
}
__device__ __forceinline__ uint32_t h2ex2(uint32_t a) {
    uint32_t d; asm("ex2.approx.f16x2 %0, %1;" : "=r"(d) : "r"(a)); return d;
}
// packed fp16x2 = {lo half: first arg, hi half: second arg}
__device__ __forceinline__ uint32_t pack_f16x2(float lo, float hi) {
    uint32_t d;
    asm("cvt.rn.f16x2.f32 %0, %1, %2;" : "=r"(d) : "f"(hi), "f"(lo));
    return d;
}
__device__ __forceinline__ void cp_async16(uint32_t dst, const void* src) {
    asm volatile("cp.async.cg.shared.global [%0], [%1], 16;"
                 :: "r"(dst), "l"(src));
}
#define CP_COMMIT() asm volatile("cp.async.commit_group;" ::: "memory")
#define CP_WAIT(n)  asm volatile("cp.async.wait_group %0;" :: "n"(n) : "memory")
#define ONES2 0x3C003C00u   /* fp16x2 {1.0, 1.0} */

// ---------------- LayerNorm -> fp16 (warp-per-row) ---------------------------
__global__ void __launch_bounds__(256) ln_f16_kernel(
    const float* __restrict__ x, const float* __restrict__ g,
    const float* __restrict__ b, __half* __restrict__ out)
{
    const int row  = blockIdx.x * 8 + (threadIdx.x >> 5);
    const int lane = threadIdx.x & 31;
    const float4* xr = (const float4*)(x + (size_t)row * D_);
    const float4* gv = (const float4*)g;
    const float4* bv = (const float4*)b;

    float4 v[6];
    float s = 0.f;
    #pragma unroll
    for (int k = 0; k < 6; k++) {
        v[k] = xr[lane + 32 * k];
        s += v[k].x + v[k].y + v[k].z + v[k].w;
    }
    #pragma unroll
    for (int o = 16; o; o >>= 1) s += __shfl_xor_sync(0xffffffffu, s, o);
    const float mu = s * (1.0f / D_);

    float q = 0.f;
    #pragma unroll
    for (int k = 0; k < 6; k++) {
        v[k].x -= mu; v[k].y -= mu; v[k].z -= mu; v[k].w -= mu;
        q += v[k].x * v[k].x + v[k].y * v[k].y + v[k].z * v[k].z + v[k].w * v[k].w;
    }
    #pragma unroll
    for (int o = 16; o; o >>= 1) q += __shfl_xor_sync(0xffffffffu, q, o);
    const float rs = rsqrtf(q * (1.0f / D_) + EPS_);

    uint2* hp = (uint2*)(out + (size_t)row * D_);
    #pragma unroll
    for (int k = 0; k < 6; k++) {
        const int i4 = lane + 32 * k;
        float4 gg = gv[i4], bb = bv[i4];
        float o0 = v[k].x * rs * gg.x + bb.x;
        float o1 = v[k].y * rs * gg.y + bb.y;
        float o2 = v[k].z * rs * gg.z + bb.z;
        float o3 = v[k].w * rs * gg.w + bb.w;
        hp[i4] = make_uint2(pack_f16x2(o0, o1), pack_f16x2(o2, o3));
    }
}

// ---------------- weight transpose + cast: w[K,N] -> wt[N,K] fp16 -----------
__global__ void __launch_bounds__(256) wcast_kernel(
    const float* __restrict__ w, __half* __restrict__ wt, int K, int N)
{
    __shared__ float t[32][33];
    const int n0 = blockIdx.x * 32, k0 = blockIdx.y * 32;
    const int tx = threadIdx.x & 31, ty = threadIdx.x >> 5;
    #pragma unroll
    for (int j = 0; j < 4; j++) {
        int k = ty + j * 8;
        t[k][tx] = w[(size_t)(k0 + k) * N + n0 + tx];
    }
    __syncthreads();
    #pragma unroll
    for (int j = 0; j < 4; j++) {
        int n = ty + j * 8;
        wt[(size_t)(n0 + n) * K + k0 + tx] = __float2half(t[tx][n]);
    }
}

// ---------------- MMA GEMM: C[M,N] = A[M,K] @ B[N,K]^T, fp16 single-pass ----
// 128x128 tile, K chunk 64, 256 threads, 8 warps (4m x 2n), warp 32x64.
// cp.async 2-stage, 2 CTAs/SM.
// EPI: 1 bias+GELU->fp16 ; 3 bias->fp16
#define BM   128
#define BN   128
#define BKC  64
#define ROWB 144          /* 64 fp16 = 128B + 16B pad */
#define TILEB (128 * ROWB)     /* 18432 */
#define STAGEB (2 * TILEB)     /* 36864 */
#define GEMM_SMEM (2 * STAGEB) /* 73728 */

template <int EPI>
__global__ void __launch_bounds__(256, 2) gemm_mma(
    const __half* __restrict__ A_g, const __half* __restrict__ B_g,
    const float* __restrict__ bias,
    __half* __restrict__ Ch, int M, int N, int K)
{
    extern __shared__ char dsm[];
    const uint32_t sbase = smem_u32(dsm);

    const int tid  = threadIdx.x;
    const int lane = tid & 31;
    const int wid  = tid >> 5;
    const int wm   = wid & 3;
    const int wn   = wid >> 2;
    const int m0   = blockIdx.y * BM;
    const int n0   = blockIdx.x * BN;

    const int a_row = lane & 15;
    const int a_col = (lane >> 4) << 3;
    const uint32_t offA = (uint32_t)((wm * 32 + a_row) * ROWB + a_col * 2);
    const int b_row = (lane & 7) | ((lane >> 4) << 3);
    const int b_col = ((lane >> 3) & 1) << 3;
    const uint32_t offB = (uint32_t)(TILEB + (wn * 64 + b_row) * ROWB + b_col * 2);

    float acc[2][8][4];
    #pragma unroll
    for (int i = 0; i < 2; i++)
        #pragma unroll
        for (int j = 0; j < 8; j++)
            #pragma unroll
            for (int k = 0; k < 4; k++) acc[i][j][k] = 0.f;

    const int ldu = K >> 3;
    const uint4* ga = (const uint4*)A_g;
    const uint4* gb = (const uint4*)B_g;

    const int nchunks = K / BKC;

    auto issue = [&](int stage, int ch) {
        const int k0u = ch * (BKC / 8);
        const uint32_t so = sbase + (uint32_t)stage * STAGEB;
        #pragma unroll
        for (int i = 0; i < 4; i++) {
            const int idx = tid + i * 256;
            const int r = idx >> 3, q = idx & 7;
            const uint32_t d = so + (uint32_t)(r * ROWB + q * 16);
            cp_async16(d,         ga + (size_t)(m0 + r) * ldu + k0u + q);
            cp_async16(d + TILEB, gb + (size_t)(n0 + r) * ldu + k0u + q);
        }
    };

    issue(0, 0);
    CP_COMMIT();

    for (int ch = 0; ch < nchunks; ch++) {
        if (ch + 1 < nchunks) {
            issue((ch + 1) & 1, ch + 1);
            CP_COMMIT();
            CP_WAIT(1);
        } else {
            CP_WAIT(0);
        }
        __syncthreads();

        const uint32_t st = sbase + (uint32_t)(ch & 1) * STAGEB;
        const uint32_t aT = st + offA;
        const uint32_t bT = st + offB;

        #pragma unroll
        for (int ks = 0; ks < BKC; ks += 16) {
            uint32_t ah[2][4];
            #pragma unroll
            for (int mt = 0; mt < 2; mt++)
                ldsm_x4(ah[mt], aT + mt * (16 * ROWB) + ks * 2);
            #pragma unroll
            for (int np = 0; np < 4; np++) {
                uint32_t bh[4];
                ldsm_x4(bh, bT + np * (16 * ROWB) + ks * 2);
                #pragma unroll
                for (int mt = 0; mt < 2; mt++) {
                    mma16816(acc[mt][2 * np],     ah[mt], bh[0], bh[1]);
                    mma16816(acc[mt][2 * np + 1], ah[mt], bh[2], bh[3]);
                }
            }
        }
        __syncthreads();
    }

    // epilogue
    const int lr = lane >> 2;
    const int lc = (lane & 3) * 2;
    #pragma unroll
    for (int mt = 0; mt < 2; mt++) {
        #pragma unroll
        for (int nt = 0; nt < 8; nt++) {
            #pragma unroll
            for (int hh = 0; hh < 2; hh++) {
                const int gr = m0 + wm * 32 + mt * 16 + lr + hh * 8;
                const int gc = n0 + wn * 64 + nt * 8 + lc;
                float v0 = acc[mt][nt][hh * 2 + 0] + bias[gc];
                float v1 = acc[mt][nt][hh * 2 + 1] + bias[gc + 1];
                const size_t go = (size_t)gr * N + gc;
                if (EPI == 1) {
                    v0 = 0.5f * v0 * (1.0f + erff(v0 * 0.70710678118654752f));
                    v1 = 0.5f * v1 * (1.0f + erff(v1 * 0.70710678118654752f));
                }
                ((uint32_t*)Ch)[go >> 1] = pack_f16x2(v0, v1);
            }
        }
    }
}

// ---------------- MLP2 split-K GEMM: partials, no epilogue math --------------
// Same 128x128 tile / inner loop as gemm_mma. blockIdx.z selects K half.
__global__ void __launch_bounds__(256, 2) gemm_splitk(
    const __half* __restrict__ A_g, const __half* __restrict__ B_g,
    float* __restrict__ part, int M, int N, int Kfull)
{
    extern __shared__ char dsm[];
    const uint32_t sbase = smem_u32(dsm);

    const int tid  = threadIdx.x;
    const int lane = tid & 31;
    const int wid  = tid >> 5;
    const int wm   = wid & 3;
    const int wn   = wid >> 2;
    const int m0   = blockIdx.y * BM;
    const int n0   = blockIdx.x * BN;
    const int kz   = blockIdx.z;
    const int Keff = Kfull >> 1;

    const int a_row = lane & 15;
    const int a_col = (lane >> 4) << 3;
    const uint32_t offA = (uint32_t)((wm * 32 + a_row) * ROWB + a_col * 2);
    const int b_row = (lane & 7) | ((lane >> 4) << 3);
    const int b_col = ((lane >> 3) & 1) << 3;
    const uint32_t offB = (uint32_t)(TILEB + (wn * 64 + b_row) * ROWB + b_col * 2);

    float acc[2][8][4];
    #pragma unroll
    for (int i = 0; i < 2; i++)
        #pragma unroll
        for (int j = 0; j < 8; j++)
            #pragma unroll
            for (int k = 0; k < 4; k++) acc[i][j][k] = 0.f;

    const int ldu = Kfull >> 3;
    const int kbase = kz * (Keff >> 3);   // uint4 offset of this K half
    const uint4* ga = (const uint4*)A_g;
    const uint4* gb = (const uint4*)B_g;

    const int nchunks = Keff / BKC;

    auto issue = [&](int stage, int ch) {
        const int k0u = kbase + ch * (BKC / 8);
        const uint32_t so = sbase + (uint32_t)stage * STAGEB;
        #pragma unroll
        for (int i = 0; i < 4; i++) {
            const int idx = tid + i * 256;
            const int r = idx >> 3, q = idx & 7;
            const uint32_t d = so + (uint32_t)(r * ROWB + q * 16);
            cp_async16(d,         ga + (size_t)(m0 + r) * ldu + k0u + q);
            cp_async16(d + TILEB, gb + (size_t)(n0 + r) * ldu + k0u + q);
        }
    };

    issue(0, 0);
    CP_COMMIT();

    for (int ch = 0; ch < nchunks; ch++) {
        if (ch + 1 < nchunks) {
            issue((ch + 1) & 1, ch + 1);
            CP_COMMIT();
            CP_WAIT(1);
        } else {
            CP_WAIT(0);
        }
        __syncthreads();

        const uint32_t st = sbase + (uint32_t)(ch & 1) * STAGEB;
        const uint32_t aT = st + offA;
        const uint32_t bT = st + offB;

        #pragma unroll
        for (int ks = 0; ks < BKC; ks += 16) {
            uint32_t ah[2][4];
            #pragma unroll
            for (int mt = 0; mt < 2; mt++)
                ldsm_x4(ah[mt], aT + mt * (16 * ROWB) + ks * 2);
            #pragma unroll
            for (int np = 0; np < 4; np++) {
                uint32_t bh[4];
                ldsm_x4(bh, bT + np * (16 * ROWB) + ks * 2);
                #pragma unroll
                for (int mt = 0; mt < 2; mt++) {
                    mma16816(acc[mt][2 * np],     ah[mt], bh[0], bh[1]);
                    mma16816(acc[mt][2 * np + 1], ah[mt], bh[2], bh[3]);
                }
            }
        }
        __syncthreads();
    }

    float* dst = part + (size_t)kz * NTOK * D_;
    const int lr = lane >> 2;
    const int lc = (lane & 3) * 2;
    #pragma unroll
    for (int mt = 0; mt < 2; mt++) {
        #pragma unroll
        for (int nt = 0; nt < 8; nt++) {
            #pragma unroll
            for (int hh = 0; hh < 2; hh++) {
                const int gr = m0 + wm * 32 + mt * 16 + lr + hh * 8;
                const int gc = n0 + wn * 64 + nt * 8 + lc;
                const size_t go = (size_t)gr * N + gc;
                *(float2*)&dst[go] = make_float2(acc[mt][nt][hh * 2],
                                                 acc[mt][nt][hh * 2 + 1]);
            }
        }
    }
}

// ---------------- MLP2 combine: out = (p0+p1+bias)*0.9 + x1 ------------------
__global__ void __launch_bounds__(256) mlp2_combine(
    const float* __restrict__ part, const float* __restrict__ bias,
    const float* __restrict__ x1, float* __restrict__ out)
{
    const int i4 = blockIdx.x * 256 + threadIdx.x;   // float4 index
    const float4* p0 = (const float4*)part;
    const float4* p1 = p0 + (NTOK * D_) / 4;
    float4 a = p0[i4], b = p1[i4];
    float4 bb = ((const float4*)bias)[i4 % (D_ / 4)];
    float4 xx = ((const float4*)x1)[i4];
    float4 o;
    o.x = (a.x + b.x + bb.x) * SURV_ + xx.x;
    o.y = (a.y + b.y + bb.y) * SURV_ + xx.y;
    o.z = (a.z + b.z + bb.z) * SURV_ + xx.z;
    o.w = (a.w + b.w + bb.w) * SURV_ + xx.w;
    ((float4*)out)[i4] = o;
}

// ---------------- Flash attention v3 (R10 config, proven) --------------------
#define FQT 64
#define KT  64
#define QB_  9216                  /* 64 rows * 144B */
#define KB_  9216
#define FLASH_SMEM (QB_ + 4 * KB_) /* 46080 */

__global__ void __launch_bounds__(128) flash_mma(
    const __half* __restrict__ qkv, const float* __restrict__ x,
    float* __restrict__ x1)
{
    extern __shared__ char fsm[];
    const uint32_t sb = smem_u32(fsm);

    const int t = threadIdx.x;
    const int lane = t & 31, wid = t >> 5;
    const int qt = blockIdx.x, h = blockIdx.y, b = blockIdx.z;
    const size_t base = (size_t)b * P_ * D3_;
    const int q0 = qt * FQT, hc = h * 64;

    #pragma unroll
    for (int i = 0; i < 4; i++) {
        int idx = t + i * 128;
        int r = idx >> 3, c8 = (idx & 7) << 3;
        *(uint4*)(fsm + r * 144 + c8 * 2) =
            *(const uint4*)(qkv + base + (size_t)(q0 + r) * D3_ + hc + c8);
    }

    auto issueKV = [&](int stage, int kt) {
        const int k0 = kt * KT;
        const uint32_t kb = sb + QB_ + (uint32_t)stage * KB_;
        const uint32_t vb = sb + QB_ + 2 * KB_ + (uint32_t)stage * KB_;
        #pragma unroll
        for (int i = 0; i < 4; i++) {
            int idx = t + i * 128;
            int r = idx >> 3, c8 = (idx & 7) << 3;
            cp_async16(kb + r * 144 + c8 * 2,
                       qkv + base + (size_t)(k0 + r) * D3_ + D_ + hc + c8);
            cp_async16(vb + r * 144 + c8 * 2,
                       qkv + base + (size_t)(k0 + r) * D3_ + 2 * D_ + hc + c8);
        }
    };

    issueKV(0, 0);
    CP_COMMIT();
    __syncthreads();

    uint32_t qf[4][4];
    {
        const int qr = lane & 15;
        const int qc = (lane >> 4) << 3;
        #pragma unroll
        for (int ks = 0; ks < 4; ks++)
            ldsm_x4(qf[ks], sb + (wid * 16 + qr) * 144 + (ks * 16 + qc) * 2);
    }

    float mrow[2] = {-1e30f, -1e30f};
    float lrow[2] = {0.f, 0.f};
    float o[8][4];
    #pragma unroll
    for (int i = 0; i < 8; i++)
        #pragma unroll
        for (int j = 0; j < 4; j++) o[i][j] = 0.f;

    const float SCL = 0.18033688011112042f;  // (1/8) * log2(e)

    const int krow = (lane & 7) + ((lane >> 4) << 3);
    const int kcol = ((lane >> 3) & 1) << 3;
    const int vrow = (lane & 7) + (((lane >> 3) & 1) << 3);
    const int vcol = (lane >> 4) << 3;

    const int niter = P_ / KT;
    for (int kt = 0; kt < niter; kt++) {
        if (kt + 1 < niter) {
            issueKV((kt + 1) & 1, kt + 1);
            CP_COMMIT();
            CP_WAIT(1);
        } else {
            CP_WAIT(0);
        }
        __syncthreads();

        const uint32_t kst = sb + QB_ + (uint32_t)(kt & 1) * KB_;
        const uint32_t vst = sb + QB_ + 2 * KB_ + (uint32_t)(kt & 1) * KB_;

        float s[8][4];
        #pragma unroll
        for (int i = 0; i < 8; i++)
            #pragma unroll
            for (int j = 0; j < 4; j++) s[i][j] = 0.f;
        #pragma unroll
        for (int ks = 0; ks < 4; ks++) {
            #pragma unroll
            for (int tp = 0; tp < 4; tp++) {
                uint32_t kf[4];
                ldsm_x4(kf, kst + (tp * 16 + krow) * 144 + (ks * 16 + kcol) * 2);
                mma16816(s[2 * tp],     qf[ks], kf[0], kf[1]);
                mma16816(s[2 * tp + 1], qf[ks], kf[2], kf[3]);
            }
        }

        float pm0 = -1e30f, pm1 = -1e30f;
        #pragma unroll
        for (int nt = 0; nt < 8; nt++) {
            pm0 = fmaxf(pm0, fmaxf(s[nt][0], s[nt][1]));
            pm1 = fmaxf(pm1, fmaxf(s[nt][2], s[nt][3]));
        }
        pm0 = fmaxf(pm0, __shfl_xor_sync(0xffffffffu, pm0, 1));
        pm0 = fmaxf(pm0, __shfl_xor_sync(0xffffffffu, pm0, 2));
        pm1 = fmaxf(pm1, __shfl_xor_sync(0xffffffffu, pm1, 1));
        pm1 = fmaxf(pm1, __shfl_xor_sync(0xffffffffu, pm1, 2));
        const float mn0 = fmaxf(mrow[0], pm0);
        const float mn1 = fmaxf(mrow[1], pm1);
        const float f0 = ex2f((mrow[0] - mn0) * SCL);
        const float f1 = ex2f((mrow[1] - mn1) * SCL);

        uint32_t pf[4][4];
        #pragma unroll
        for (int ks = 0; ks < 4; ks++) {
            pf[ks][0] = h2ex2(pack_f16x2((s[2 * ks][0] - mn0) * SCL,
                                         (s[2 * ks][1] - mn0) * SCL));
            pf[ks][1] = h2ex2(pack_f16x2((s[2 * ks][2] - mn1) * SCL,
                                         (s[2 * ks][3] - mn1) * SCL));
            pf[ks][2] = h2ex2(pack_f16x2((s[2 * ks + 1][0] - mn0) * SCL,
                                         (s[2 * ks + 1][1] - mn0) * SCL));
            pf[ks][3] = h2ex2(pack_f16x2((s[2 * ks + 1][2] - mn1) * SCL,
                                         (s[2 * ks + 1][3] - mn1) * SCL));
        }

        float la[4] = {0.f, 0.f, 0.f, 0.f};
        #pragma unroll
        for (int ks = 0; ks < 4; ks++)
            mma16816(la, pf[ks], ONES2, ONES2);

        lrow[0] = lrow[0] * f0 + la[0];
        lrow[1] = lrow[1] * f1 + la[2];
        mrow[0] = mn0;
        mrow[1] = mn1;

        #pragma unroll
        for (int nt = 0; nt < 8; nt++) {
            o[nt][0] *= f0; o[nt][1] *= f0;
            o[nt][2] *= f1; o[nt][3] *= f1;
        }

        #pragma unroll
        for (int ks = 0; ks < 4; ks++) {
            #pragma unroll
            for (int tp = 0; tp < 4; tp++) {
                uint32_t vf[4];
                ldsm_x4_t(vf, vst + (ks * 16 + vrow) * 144 + (tp * 16 + vcol) * 2);
                mma16816(o[2 * tp],     pf[ks], vf[0], vf[1]);
                mma16816(o[2 * tp + 1], pf[ks], vf[2], vf[3]);
            }
        }
        __syncthreads();
    }

    const float inv0 = 1.0f / lrow[0];
    const float inv1 = 1.0f / lrow[1];
    const int r0 = q0 + wid * 16 + (lane >> 2);
    const size_t row0 = ((size_t)b * P_ + r0) * D_ + hc + (lane & 3) * 2;
    const size_t row1 = row0 + 8 * D_;
    #pragma unroll
    for (int nt = 0; nt < 8; nt++) {
        float2 xa = *(const float2*)&x[row0 + nt * 8];
        float2 ra;
        ra.x = o[nt][0] * inv0 * SURV_ + xa.x;
        ra.y = o[nt][1] * inv0 * SURV_ + xa.y;
        *(float2*)&x1[row0 + nt * 8] = ra;
        float2 xb = *(const float2*)&x[row1 + nt * 8];
        float2 rb;
        rb.x = o[nt][2] * inv1 * SURV_ + xb.x;
        rb.y = o[nt][3] * inv1 * SURV_ + xb.y;
        *(float2*)&x1[row1 + nt * 8] = rb;
    }
}

// ---------------- launch ----------------------------------------------------
extern "C" void kernel_launch(void* const* d_in, const int* in_sizes, int n_in,
                              void* d_out, int out_size)
{
    const float* x     = (const float*)d_in[0];
    const float* ln1_g = (const float*)d_in[1];
    const float* ln1_b = (const float*)d_in[2];
    const float* w_qkv = (const float*)d_in[3];
    const float* b_qkv = (const float*)d_in[4];
    const float* ln2_g = (const float*)d_in[5];
    const float* ln2_b = (const float*)d_in[6];
    const float* w1    = (const float*)d_in[7];
    const float* b1    = (const float*)d_in[8];
    const float* w2    = (const float*)d_in[9];
    const float* b2    = (const float*)d_in[10];
    float* out = (float*)d_out;

    __half *h, *qkvh, *ffn, *wq, *w1t, *w2t;
    float *x1, *part;
    cudaGetSymbolAddress((void**)&h,    g_h);
    cudaGetSymbolAddress((void**)&qkvh, g_qkvh);
    cudaGetSymbolAddress((void**)&x1,   g_x1);
    cudaGetSymbolAddress((void**)&ffn,  g_ffn);
    cudaGetSymbolAddress((void**)&part, g_part);
    cudaGetSymbolAddress((void**)&wq,   g_wq);
    cudaGetSymbolAddress((void**)&w1t,  g_w1);
    cudaGetSymbolAddress((void**)&w2t,  g_w2);

    cudaFuncSetAttribute(gemm_mma<1>,
                         cudaFuncAttributeMaxDynamicSharedMemorySize, GEMM_SMEM);
    cudaFuncSetAttribute(gemm_mma<3>,
                         cudaFuncAttributeMaxDynamicSharedMemorySize, GEMM_SMEM);
    cudaFuncSetAttribute(gemm_splitk,
                         cudaFuncAttributeMaxDynamicSharedMemorySize, GEMM_SMEM);
    cudaFuncSetAttribute(flash_mma,
                         cudaFuncAttributeMaxDynamicSharedMemorySize, FLASH_SMEM);

    // weight transpose + cast
    wcast_kernel<<<dim3(D3_ / 32, D_ / 32), 256>>>(w_qkv, wq, D_, D3_);
    wcast_kernel<<<dim3(DFF_ / 32, D_ / 32), 256>>>(w1, w1t, D_, DFF_);
    wcast_kernel<<<dim3(D_ / 32, DFF_ / 32), 256>>>(w2, w2t, DFF_, D_);

    // 1) LN1 -> fp16
    ln_f16_kernel<<<NTOK / 8, 256>>>(x, ln1_g, ln1_b, h);
    // 2) QKV projection -> fp16
    gemm_mma<3><<<dim3(D3_ / BN, NTOK / BM), 256, GEMM_SMEM>>>(
        h, wq, b_qkv, qkvh, NTOK, D3_, D_);
    // 3) attention + residual -> x1
    flash_mma<<<dim3(P_ / FQT, H_, B_), 128, FLASH_SMEM>>>(qkvh, x, x1);
    // 4) LN2 -> fp16
    ln_f16_kernel<<<NTOK / 8, 256>>>(x1, ln2_g, ln2_b, h);
    // 5) MLP up + GELU -> fp16
    gemm_mma<1><<<dim3(DFF_ / BN, NTOK / BM), 256, GEMM_SMEM>>>(
        h, w1t, b1, ffn, NTOK, DFF_, D_);
    // 6) MLP down, split-K=2 -> fp32 partials
    gemm_splitk<<<dim3(D_ / BN, NTOK / BM, 2), 256, GEMM_SMEM>>>(
        ffn, w2t, part, NTOK, D_, DFF_);
    // 7) combine partials + bias, droppath, residual -> out
    mlp2_combine<<<(NTOK * D_ / 4) / 256, 256>>>(part, b2, x1, out);
}

// round 14
// speedup vs baseline: 1.0096x; 1.0007x over previous
#include <cuda_runtime.h>
#include <cuda_fp16.h>
#include <math.h>
#include <stdint.h>

#define D_    768
#define P_    2048
#define B_    4
#define H_    12
#define DFF_  3072
#define NTOK  (B_ * P_)      /* 8192 */
#define D3_   (3 * D_)       /* 2304 */
#define EPS_  1e-3f
#define SURV_ 0.9f

// ---------------- scratch (static device globals) ---------------------------
__device__ __half g_h   [NTOK * D_];     // LN output, fp16
__device__ __half g_qkvh[NTOK * D3_];    // fp16 QKV
__device__ float  g_x1  [NTOK * D_];
__device__ __half g_ffn [NTOK * DFF_];   // MLP hidden, fp16
// transposed weights: [N, K] layout, fp16
__device__ __half g_wq[D3_ * D_];
__device__ __half g_w1[DFF_ * D_];
__device__ __half g_w2[D_ * DFF_];

// ---------------- helpers ----------------------------------------------------
__device__ __forceinline__ uint32_t smem_u32(const void* p) {
    uint32_t a;
    asm("{ .reg .u64 t; cvta.to.shared.u64 t, %1; cvt.u32.u64 %0, t; }"
        : "=r"(a) : "l"(p));
    return a;
}
__device__ __forceinline__ void ldsm_x4(uint32_t* r, uint32_t addr) {
    asm volatile("ldmatrix.sync.aligned.m8n8.x4.shared.b16 {%0,%1,%2,%3}, [%4];"
                 : "=r"(r[0]), "=r"(r[1]), "=r"(r[2]), "=r"(r[3]) : "r"(addr));
}
__device__ __forceinline__ void ldsm_x4_t(uint32_t* r, uint32_t addr) {
    asm volatile("ldmatrix.sync.aligned.m8n8.x4.trans.shared.b16 {%0,%1,%2,%3}, [%4];"
                 : "=r"(r[0]), "=r"(r[1]), "=r"(r[2]), "=r"(r[3]) : "r"(addr));
}
__device__ __forceinline__ void mma16816(float* c, const uint32_t* a,
                                         uint32_t b0, uint32_t b1) {
    asm volatile(
        "mma.sync.aligned.m16n8k16.row.col.f32.f16.f16.f32 "
        "{%0,%1,%2,%3}, {%4,%5,%6,%7}, {%8,%9}, {%0,%1,%2,%3};"
        : "+f"(c[0]), "+f"(c[1]), "+f"(c[2]), "+f"(c[3])
        : "r"(a[0]), "r"(a[1]), "r"(a[2]), "r"(a[3]), "r"(b0), "r"(b1));
}
__device__ __forceinline__ float ex2f(float x) {
    float y; asm("ex2.approx.f32 %0, %1;" : "=f"(y) : "f"(x)); return y;
}
__device__ __forceinline__ uint32_t h2ex2(uint32_t a) {
    uint32_t d; asm("ex2.approx.f16x2 %0, %1;" : "=r"(d) : "r"(a)); return d;
}
// packed fp16x2 = {lo half: first arg, hi half: second arg}
__device__ __forceinline__ uint32_t pack_f16x2(float lo, float hi) {
    uint32_t d;
    asm("cvt.rn.f16x2.f32 %0, %1, %2;" : "=r"(d) : "f"(hi), "f"(lo));
    return d;
}
__device__ __forceinline__ float2 h2f2(uint32_t p) {
    __half2 h = *(__half2*)&p;
    return __half22float2(h);
}
__device__ __forceinline__ void cp_async16(uint32_t dst, const void* src) {
    asm volatile("cp.async.cg.shared.global [%0], [%1], 16;"
                 :: "r"(dst), "l"(src));
}
#define CP_COMMIT() asm volatile("cp.async.commit_group;" ::: "memory")
#define CP_WAIT(n)  asm volatile("cp.async.wait_group %0;" :: "n"(n) : "memory")

// ---------------- LayerNorm -> fp16 (warp-per-row) ---------------------------
__global__ void __launch_bounds__(256) ln_f16_kernel(
    const float* __restrict__ x, const float* __restrict__ g,
    const float* __restrict__ b, __half* __restrict__ out)
{
    const int row  = blockIdx.x * 8 + (threadIdx.x >> 5);
    const int lane = threadIdx.x & 31;
    const float4* xr = (const float4*)(x + (size_t)row * D_);
    const float4* gv = (const float4*)g;
    const float4* bv = (const float4*)b;

    float4 v[6];
    float s = 0.f;
    #pragma unroll
    for (int k = 0; k < 6; k++) {
        v[k] = xr[lane + 32 * k];
        s += v[k].x + v[k].y + v[k].z + v[k].w;
    }
    #pragma unroll
    for (int o = 16; o; o >>= 1) s += __shfl_xor_sync(0xffffffffu, s, o);
    const float mu = s * (1.0f / D_);

    float q = 0.f;
    #pragma unroll
    for (int k = 0; k < 6; k++) {
        v[k].x -= mu; v[k].y -= mu; v[k].z -= mu; v[k].w -= mu;
        q += v[k].x * v[k].x + v[k].y * v[k].y + v[k].z * v[k].z + v[k].w * v[k].w;
    }
    #pragma unroll
    for (int o = 16; o; o >>= 1) q += __shfl_xor_sync(0xffffffffu, q, o);
    const float rs = rsqrtf(q * (1.0f / D_) + EPS_);

    uint2* hp = (uint2*)(out + (size_t)row * D_);
    #pragma unroll
    for (int k = 0; k < 6; k++) {
        const int i4 = lane + 32 * k;
        float4 gg = gv[i4], bb = bv[i4];
        float o0 = v[k].x * rs * gg.x + bb.x;
        float o1 = v[k].y * rs * gg.y + bb.y;
        float o2 = v[k].z * rs * gg.z + bb.z;
        float o3 = v[k].w * rs * gg.w + bb.w;
        hp[i4] = make_uint2(pack_f16x2(o0, o1), pack_f16x2(o2, o3));
    }
}

// ---------------- weight transpose + cast: w[K,N] -> wt[N,K] fp16 -----------
__global__ void __launch_bounds__(256) wcast_kernel(
    const float* __restrict__ w, __half* __restrict__ wt, int K, int N)
{
    __shared__ float t[32][33];
    const int n0 = blockIdx.x * 32, k0 = blockIdx.y * 32;
    const int tx = threadIdx.x & 31, ty = threadIdx.x >> 5;
    #pragma unroll
    for (int j = 0; j < 4; j++) {
        int k = ty + j * 8;
        t[k][tx] = w[(size_t)(k0 + k) * N + n0 + tx];
    }
    __syncthreads();
    #pragma unroll
    for (int j = 0; j < 4; j++) {
        int n = ty + j * 8;
        wt[(size_t)(n0 + n) * K + k0 + tx] = __float2half(t[tx][n]);
    }
}

// ---------------- MMA GEMM: C[M,N] = A[M,K] @ B[N,K]^T, fp16 single-pass ----
// 128x128 tile, K chunk 64, 256 threads, 8 warps (4m x 2n), warp 32x64.
// cp.async 2-stage, 2 CTAs/SM.
// EPI: 1 bias+GELU->fp16 ; 2 bias,*0.9+res->fp32 ; 3 bias->fp16
#define BM   128
#define BN   128
#define BKC  64
#define ROWB 144          /* 64 fp16 = 128B + 16B pad */
#define TILEB (128 * ROWB)     /* 18432 */
#define STAGEB (2 * TILEB)     /* 36864 */
#define GEMM_SMEM (2 * STAGEB) /* 73728 */

template <int EPI>
__global__ void __launch_bounds__(256, 2) gemm_mma(
    const __half* __restrict__ A_g, const __half* __restrict__ B_g,
    const float* __restrict__ bias, const float* __restrict__ res,
    float* __restrict__ Cf, __half* __restrict__ Ch,
    int M, int N, int K)
{
    extern __shared__ char dsm[];
    const uint32_t sbase = smem_u32(dsm);

    const int tid  = threadIdx.x;
    const int lane = tid & 31;
    const int wid  = tid >> 5;
    const int wm   = wid & 3;
    const int wn   = wid >> 2;
    const int m0   = blockIdx.y * BM;
    const int n0   = blockIdx.x * BN;

    const int a_row = lane & 15;
    const int a_col = (lane >> 4) << 3;
    const uint32_t offA = (uint32_t)((wm * 32 + a_row) * ROWB + a_col * 2);
    const int b_row = (lane & 7) | ((lane >> 4) << 3);
    const int b_col = ((lane >> 3) & 1) << 3;
    const uint32_t offB = (uint32_t)(TILEB + (wn * 64 + b_row) * ROWB + b_col * 2);

    float acc[2][8][4];
    #pragma unroll
    for (int i = 0; i < 2; i++)
        #pragma unroll
        for (int j = 0; j < 8; j++)
            #pragma unroll
            for (int k = 0; k < 4; k++) acc[i][j][k] = 0.f;

    const int ldu = K >> 3;
    const uint4* ga = (const uint4*)A_g;
    const uint4* gb = (const uint4*)B_g;

    const int nchunks = K / BKC;

    auto issue = [&](int stage, int ch) {
        const int k0u = ch * (BKC / 8);
        const uint32_t so = sbase + (uint32_t)stage * STAGEB;
        #pragma unroll
        for (int i = 0; i < 4; i++) {
            const int idx = tid + i * 256;
            const int r = idx >> 3, q = idx & 7;
            const uint32_t d = so + (uint32_t)(r * ROWB + q * 16);
            cp_async16(d,         ga + (size_t)(m0 + r) * ldu + k0u + q);
            cp_async16(d + TILEB, gb + (size_t)(n0 + r) * ldu + k0u + q);
        }
    };

    issue(0, 0);
    CP_COMMIT();

    for (int ch = 0; ch < nchunks; ch++) {
        if (ch + 1 < nchunks) {
            issue((ch + 1) & 1, ch + 1);
            CP_COMMIT();
            CP_WAIT(1);
        } else {
            CP_WAIT(0);
        }
        __syncthreads();

        const uint32_t st = sbase + (uint32_t)(ch & 1) * STAGEB;
        const uint32_t aT = st + offA;
        const uint32_t bT = st + offB;

        #pragma unroll
        for (int ks = 0; ks < BKC; ks += 16) {
            uint32_t ah[2][4];
            #pragma unroll
            for (int mt = 0; mt < 2; mt++)
                ldsm_x4(ah[mt], aT + mt * (16 * ROWB) + ks * 2);
            #pragma unroll
            for (int np = 0; np < 4; np++) {
                uint32_t bh[4];
                ldsm_x4(bh, bT + np * (16 * ROWB) + ks * 2);
                #pragma unroll
                for (int mt = 0; mt < 2; mt++) {
                    mma16816(acc[mt][2 * np],     ah[mt], bh[0], bh[1]);
                    mma16816(acc[mt][2 * np + 1], ah[mt], bh[2], bh[3]);
                }
            }
        }
        __syncthreads();
    }

    // epilogue
    const int lr = lane >> 2;
    const int lc = (lane & 3) * 2;
    #pragma unroll
    for (int mt = 0; mt < 2; mt++) {
        #pragma unroll
        for (int nt = 0; nt < 8; nt++) {
            #pragma unroll
            for (int hh = 0; hh < 2; hh++) {
                const int gr = m0 + wm * 32 + mt * 16 + lr + hh * 8;
                const int gc = n0 + wn * 64 + nt * 8 + lc;
                float v0 = acc[mt][nt][hh * 2 + 0] + bias[gc];
                float v1 = acc[mt][nt][hh * 2 + 1] + bias[gc + 1];
                const size_t go = (size_t)gr * N + gc;
                if (EPI == 1) {
                    v0 = 0.5f * v0 * (1.0f + erff(v0 * 0.70710678118654752f));
                    v1 = 0.5f * v1 * (1.0f + erff(v1 * 0.70710678118654752f));
                    ((uint32_t*)Ch)[go >> 1] = pack_f16x2(v0, v1);
                } else if (EPI == 2) {
                    float2 rr = *(const float2*)&res[go];
                    float2 o2 = make_float2(v0 * SURV_ + rr.x, v1 * SURV_ + rr.y);
                    *(float2*)&Cf[go] = o2;
                } else {  // EPI == 3
                    ((uint32_t*)Ch)[go >> 1] = pack_f16x2(v0, v1);
                }
            }
        }
    }
}

// ---------------- Flash attention (champion config; row-sums on FMA pipe) ---
#define FQT 64
#define KT  64
#define QB_  9216                  /* 64 rows * 144B */
#define KB_  9216
#define FLASH_SMEM (QB_ + 4 * KB_) /* 46080 */

__global__ void __launch_bounds__(128) flash_mma(
    const __half* __restrict__ qkv, const float* __restrict__ x,
    float* __restrict__ x1)
{
    extern __shared__ char fsm[];
    const uint32_t sb = smem_u32(fsm);

    const int t = threadIdx.x;
    const int lane = t & 31, wid = t >> 5;
    const int qt = blockIdx.x, h = blockIdx.y, b = blockIdx.z;
    const size_t base = (size_t)b * P_ * D3_;
    const int q0 = qt * FQT, hc = h * 64;

    #pragma unroll
    for (int i = 0; i < 4; i++) {
        int idx = t + i * 128;
        int r = idx >> 3, c8 = (idx & 7) << 3;
        *(uint4*)(fsm + r * 144 + c8 * 2) =
            *(const uint4*)(qkv + base + (size_t)(q0 + r) * D3_ + hc + c8);
    }

    auto issueKV = [&](int stage, int kt) {
        const int k0 = kt * KT;
        const uint32_t kb = sb + QB_ + (uint32_t)stage * KB_;
        const uint32_t vb = sb + QB_ + 2 * KB_ + (uint32_t)stage * KB_;
        #pragma unroll
        for (int i = 0; i < 4; i++) {
            int idx = t + i * 128;
            int r = idx >> 3, c8 = (idx & 7) << 3;
            cp_async16(kb + r * 144 + c8 * 2,
                       qkv + base + (size_t)(k0 + r) * D3_ + D_ + hc + c8);
            cp_async16(vb + r * 144 + c8 * 2,
                       qkv + base + (size_t)(k0 + r) * D3_ + 2 * D_ + hc + c8);
        }
    };

    issueKV(0, 0);
    CP_COMMIT();
    __syncthreads();

    uint32_t qf[4][4];
    {
        const int qr = lane & 15;
        const int qc = (lane >> 4) << 3;
        #pragma unroll
        for (int ks = 0; ks < 4; ks++)
            ldsm_x4(qf[ks], sb + (wid * 16 + qr) * 144 + (ks * 16 + qc) * 2);
    }

    float mrow[2] = {-1e30f, -1e30f};
    float lrow[2] = {0.f, 0.f};
    float o[8][4];
    #pragma unroll
    for (int i = 0; i < 8; i++)
        #pragma unroll
        for (int j = 0; j < 4; j++) o[i][j] = 0.f;

    const float SCL = 0.18033688011112042f;  // (1/8) * log2(e)

    const int krow = (lane & 7) + ((lane >> 4) << 3);
    const int kcol = ((lane >> 3) & 1) << 3;
    const int vrow = (lane & 7) + (((lane >> 3) & 1) << 3);
    const int vcol = (lane >> 4) << 3;

    const int niter = P_ / KT;
    for (int kt = 0; kt < niter; kt++) {
        if (kt + 1 < niter) {
            issueKV((kt + 1) & 1, kt + 1);
            CP_COMMIT();
            CP_WAIT(1);
        } else {
            CP_WAIT(0);
        }
        __syncthreads();

        const uint32_t kst = sb + QB_ + (uint32_t)(kt & 1) * KB_;
        const uint32_t vst = sb + QB_ + 2 * KB_ + (uint32_t)(kt & 1) * KB_;

        float s[8][4];
        #pragma unroll
        for (int i = 0; i < 8; i++)
            #pragma unroll
            for (int j = 0; j < 4; j++) s[i][j] = 0.f;
        #pragma unroll
        for (int ks = 0; ks < 4; ks++) {
            #pragma unroll
            for (int tp = 0; tp < 4; tp++) {
                uint32_t kf[4];
                ldsm_x4(kf, kst + (tp * 16 + krow) * 144 + (ks * 16 + kcol) * 2);
                mma16816(s[2 * tp],     qf[ks], kf[0], kf[1]);
                mma16816(s[2 * tp + 1], qf[ks], kf[2], kf[3]);
            }
        }

        float pm0 = -1e30f, pm1 = -1e30f;
        #pragma unroll
        for (int nt = 0; nt < 8; nt++) {
            pm0 = fmaxf(pm0, fmaxf(s[nt][0], s[nt][1]));
            pm1 = fmaxf(pm1, fmaxf(s[nt][2], s[nt][3]));
        }
        pm0 = fmaxf(pm0, __shfl_xor_sync(0xffffffffu, pm0, 1));
        pm0 = fmaxf(pm0, __shfl_xor_sync(0xffffffffu, pm0, 2));
        pm1 = fmaxf(pm1, __shfl_xor_sync(0xffffffffu, pm1, 1));
        pm1 = fmaxf(pm1, __shfl_xor_sync(0xffffffffu, pm1, 2));
        const float mn0 = fmaxf(mrow[0], pm0);
        const float mn1 = fmaxf(mrow[1], pm1);
        const float f0 = ex2f((mrow[0] - mn0) * SCL);
        const float f1 = ex2f((mrow[1] - mn1) * SCL);

        uint32_t pf[4][4];
        #pragma unroll
        for (int ks = 0; ks < 4; ks++) {
            pf[ks][0] = h2ex2(pack_f16x2((s[2 * ks][0] - mn0) * SCL,
                                         (s[2 * ks][1] - mn0) * SCL));
            pf[ks][1] = h2ex2(pack_f16x2((s[2 * ks][2] - mn1) * SCL,
                                         (s[2 * ks][3] - mn1) * SCL));
            pf[ks][2] = h2ex2(pack_f16x2((s[2 * ks + 1][0] - mn0) * SCL,
                                         (s[2 * ks + 1][1] - mn0) * SCL));
            pf[ks][3] = h2ex2(pack_f16x2((s[2 * ks + 1][2] - mn1) * SCL,
                                         (s[2 * ks + 1][3] - mn1) * SCL));
        }

        // row sums of the exact fp16 P values, fp32 accumulate on FMA pipe
        // (replaces 4 ones-MMAs per iter; numerics identical — validated R12)
        float la0 = 0.f, la1 = 0.f;
        #pragma unroll
        for (int ks = 0; ks < 4; ks++) {
            float2 a = h2f2(pf[ks][0]), c = h2f2(pf[ks][2]);
            la0 += (a.x + a.y) + (c.x + c.y);
            float2 bq = h2f2(pf[ks][1]), d = h2f2(pf[ks][3]);
            la1 += (bq.x + bq.y) + (d.x + d.y);
        }
        la0 += __shfl_xor_sync(0xffffffffu, la0, 1);
        la0 += __shfl_xor_sync(0xffffffffu, la0, 2);
        la1 += __shfl_xor_sync(0xffffffffu, la1, 1);
        la1 += __shfl_xor_sync(0xffffffffu, la1, 2);

        lrow[0] = lrow[0] * f0 + la0;
        lrow[1] = lrow[1] * f1 + la1;
        mrow[0] = mn0;
        mrow[1] = mn1;

        #pragma unroll
        for (int nt = 0; nt < 8; nt++) {
            o[nt][0] *= f0; o[nt][1] *= f0;
            o[nt][2] *= f1; o[nt][3] *= f1;
        }

        #pragma unroll
        for (int ks = 0; ks < 4; ks++) {
            #pragma unroll
            for (int tp = 0; tp < 4; tp++) {
                uint32_t vf[4];
                ldsm_x4_t(vf, vst + (ks * 16 + vrow) * 144 + (tp * 16 + vcol) * 2);
                mma16816(o[2 * tp],     pf[ks], vf[0], vf[1]);
                mma16816(o[2 * tp + 1], pf[ks], vf[2], vf[3]);
            }
        }
        __syncthreads();
    }

    const float inv0 = 1.0f / lrow[0];
    const float inv1 = 1.0f / lrow[1];
    const int r0 = q0 + wid * 16 + (lane >> 2);
    const size_t row0 = ((size_t)b * P_ + r0) * D_ + hc + (lane & 3) * 2;
    const size_t row1 = row0 + 8 * D_;
    #pragma unroll
    for (int nt = 0; nt < 8; nt++) {
        float2 xa = *(const float2*)&x[row0 + nt * 8];
        float2 ra;
        ra.x = o[nt][0] * inv0 * SURV_ + xa.x;
        ra.y = o[nt][1] * inv0 * SURV_ + xa.y;
        *(float2*)&x1[row0 + nt * 8] = ra;
        float2 xb = *(const float2*)&x[row1 + nt * 8];
        float2 rb;
        rb.x = o[nt][2] * inv1 * SURV_ + xb.x;
        rb.y = o[nt][3] * inv1 * SURV_ + xb.y;
        *(float2*)&x1[row1 + nt * 8] = rb;
    }
}

// ---------------- launch ----------------------------------------------------
extern "C" void kernel_launch(void* const* d_in, const int* in_sizes, int n_in,
                              void* d_out, int out_size)
{
    const float* x     = (const float*)d_in[0];
    const float* ln1_g = (const float*)d_in[1];
    const float* ln1_b = (const float*)d_in[2];
    const float* w_qkv = (const float*)d_in[3];
    const float* b_qkv = (const float*)d_in[4];
    const float* ln2_g = (const float*)d_in[5];
    const float* ln2_b = (const float*)d_in[6];
    const float* w1    = (const float*)d_in[7];
    const float* b1    = (const float*)d_in[8];
    const float* w2    = (const float*)d_in[9];
    const float* b2    = (const float*)d_in[10];
    float* out = (float*)d_out;

    __half *h, *qkvh, *ffn, *wq, *w1t, *w2t;
    float *x1;
    cudaGetSymbolAddress((void**)&h,    g_h);
    cudaGetSymbolAddress((void**)&qkvh, g_qkvh);
    cudaGetSymbolAddress((void**)&x1,   g_x1);
    cudaGetSymbolAddress((void**)&ffn,  g_ffn);
    cudaGetSymbolAddress((void**)&wq,   g_wq);
    cudaGetSymbolAddress((void**)&w1t,  g_w1);
    cudaGetSymbolAddress((void**)&w2t,  g_w2);

    cudaFuncSetAttribute(gemm_mma<1>,
                         cudaFuncAttributeMaxDynamicSharedMemorySize, GEMM_SMEM);
    cudaFuncSetAttribute(gemm_mma<2>,
                         cudaFuncAttributeMaxDynamicSharedMemorySize, GEMM_SMEM);
    cudaFuncSetAttribute(gemm_mma<3>,
                         cudaFuncAttributeMaxDynamicSharedMemorySize, GEMM_SMEM);
    cudaFuncSetAttribute(flash_mma,
                         cudaFuncAttributeMaxDynamicSharedMemorySize, FLASH_SMEM);

    // weight transpose + cast
    wcast_kernel<<<dim3(D3_ / 32, D_ / 32), 256>>>(w_qkv, wq, D_, D3_);
    wcast_kernel<<<dim3(DFF_ / 32, D_ / 32), 256>>>(w1, w1t, D_, DFF_);
    wcast_kernel<<<dim3(D_ / 32, DFF_ / 32), 256>>>(w2, w2t, DFF_, D_);

    // 1) LN1 -> fp16
    ln_f16_kernel<<<NTOK / 8, 256>>>(x, ln1_g, ln1_b, h);
    // 2) QKV projection -> fp16
    gemm_mma<3><<<dim3(D3_ / BN, NTOK / BM), 256, GEMM_SMEM>>>(
        h, wq, b_qkv, nullptr, nullptr, qkvh, NTOK, D3_, D_);
    // 3) attention + residual -> x1
    flash_mma<<<dim3(P_ / FQT, H_, B_), 128, FLASH_SMEM>>>(qkvh, x, x1);
    // 4) LN2 -> fp16
    ln_f16_kernel<<<NTOK / 8, 256>>>(x1, ln2_g, ln2_b, h);
    // 5) MLP up + GELU -> fp16
    gemm_mma<1><<<dim3(DFF_ / BN, NTOK / BM), 256, GEMM_SMEM>>>(
        h, w1t, b1, nullptr, nullptr, ffn, NTOK, DFF_, D_);
    // 6) MLP down + droppath + residual -> out
    gemm_mma<2><<<dim3(D_ / BN, NTOK / BM), 256, GEMM_SMEM>>>(
        ffn, w2t, b2, x1, out, nullptr, NTOK, D_, DFF_);
}

// round 15
// speedup vs baseline: 1.0219x; 1.0121x over previous
#include <cuda_runtime.h>
#include <cuda_fp16.h>
#include <math.h>
#include <stdint.h>

#define D_    768
#define P_    2048
#define B_    4
#define H_    12
#define DFF_  3072
#define NTOK  (B_ * P_)      /* 8192 */
#define D3_   (3 * D_)       /* 2304 */
#define EPS_  1e-3f
#define SURV_ 0.9f

// ---------------- scratch (static device globals) ---------------------------
__device__ __half g_h   [NTOK * D_];     // LN output, fp16
__device__ __half g_qkvh[NTOK * D3_];    // fp16 QKV
__device__ float  g_x1  [NTOK * D_];
__device__ __half g_ffn [NTOK * DFF_];   // MLP hidden, fp16
// transposed weights: [N, K] layout, fp16
__device__ __half g_wq[D3_ * D_];
__device__ __half g_w1[DFF_ * D_];
__device__ __half g_w2[D_ * DFF_];

// ---------------- helpers ----------------------------------------------------
__device__ __forceinline__ uint32_t smem_u32(const void* p) {
    uint32_t a;
    asm("{ .reg .u64 t; cvta.to.shared.u64 t, %1; cvt.u32.u64 %0, t; }"
        : "=r"(a) : "l"(p));
    return a;
}
__device__ __forceinline__ void ldsm_x4(uint32_t* r, uint32_t addr) {
    asm volatile("ldmatrix.sync.aligned.m8n8.x4.shared.b16 {%0,%1,%2,%3}, [%4];"
                 : "=r"(r[0]), "=r"(r[1]), "=r"(r[2]), "=r"(r[3]) : "r"(addr));
}
__device__ __forceinline__ void ldsm_x4_t(uint32_t* r, uint32_t addr) {
    asm volatile("ldmatrix.sync.aligned.m8n8.x4.trans.shared.b16 {%0,%1,%2,%3}, [%4];"
                 : "=r"(r[0]), "=r"(r[1]), "=r"(r[2]), "=r"(r[3]) : "r"(addr));
}
__device__ __forceinline__ void mma16816(float* c, const uint32_t* a,
                                         uint32_t b0, uint32_t b1) {
    asm volatile(
        "mma.sync.aligned.m16n8k16.row.col.f32.f16.f16.f32 "
        "{%0,%1,%2,%3}, {%4,%5,%6,%7}, {%8,%9}, {%0,%1,%2,%3};"
        : "+f"(c[0]), "+f"(c[1]), "+f"(c[2]), "+f"(c[3])
        : "r"(a[0]), "r"(a[1]), "r"(a[2]), "r"(a[3]), "r"(b0), "r"(b1));
}
__device__ __forceinline__ float ex2f(float x) {
    float y; asm("ex2.approx.f32 %0, %1;" : "=f"(y) : "f"(x)); return y;
}
__device__ __forceinline__ uint32_t h2ex2(uint32_t a) {
    uint32_t d; asm("ex2.approx.f16x2 %0, %1;" : "=r"(d) : "r"(a)); return d;
}
// packed fp16x2 = {lo half: first arg, hi half: second arg}
__device__ __forceinline__ uint32_t pack_f16x2(float lo, float hi) {
    uint32_t d;
    asm("cvt.rn.f16x2.f32 %0, %1, %2;" : "=r"(d) : "f"(hi), "f"(lo));
    return d;
}
__device__ __forceinline__ void cp_async16(uint32_t dst, const void* src) {
    asm volatile("cp.async.cg.shared.global [%0], [%1], 16;"
                 :: "r"(dst), "l"(src));
}
#define CP_COMMIT() asm volatile("cp.async.commit_group;" ::: "memory")
#define CP_WAIT(n)  asm volatile("cp.async.wait_group %0;" :: "n"(n) : "memory")
#define ONES2 0x3C003C00u   /* fp16x2 {1.0, 1.0} */

// ---------------- prep bodies (identical math to proven kernels) -------------
__device__ __forceinline__ void wcast_body(
    const float* __restrict__ w, __half* __restrict__ wt,
    int K, int N, int bx, int by)
{
    __shared__ float t[32][33];
    const int n0 = bx * 32, k0 = by * 32;
    const int tx = threadIdx.x & 31, ty = threadIdx.x >> 5;
    #pragma unroll
    for (int j = 0; j < 4; j++) {
        int k = ty + j * 8;
        t[k][tx] = w[(size_t)(k0 + k) * N + n0 + tx];
    }
    __syncthreads();
    #pragma unroll
    for (int j = 0; j < 4; j++) {
        int n = ty + j * 8;
        wt[(size_t)(n0 + n) * K + k0 + tx] = __float2half(t[tx][n]);
    }
}

__device__ __forceinline__ void ln_body(
    const float* __restrict__ x, const float* __restrict__ g,
    const float* __restrict__ b, __half* __restrict__ out, int blk)
{
    const int row  = blk * 8 + (threadIdx.x >> 5);
    const int lane = threadIdx.x & 31;
    const float4* xr = (const float4*)(x + (size_t)row * D_);
    const float4* gv = (const float4*)g;
    const float4* bv = (const float4*)b;

    float4 v[6];
    float s = 0.f;
    #pragma unroll
    for (int k = 0; k < 6; k++) {
        v[k] = xr[lane + 32 * k];
        s += v[k].x + v[k].y + v[k].z + v[k].w;
    }
    #pragma unroll
    for (int o = 16; o; o >>= 1) s += __shfl_xor_sync(0xffffffffu, s, o);
    const float mu = s * (1.0f / D_);

    float q = 0.f;
    #pragma unroll
    for (int k = 0; k < 6; k++) {
        v[k].x -= mu; v[k].y -= mu; v[k].z -= mu; v[k].w -= mu;
        q += v[k].x * v[k].x + v[k].y * v[k].y + v[k].z * v[k].z + v[k].w * v[k].w;
    }
    #pragma unroll
    for (int o = 16; o; o >>= 1) q += __shfl_xor_sync(0xffffffffu, q, o);
    const float rs = rsqrtf(q * (1.0f / D_) + EPS_);

    uint2* hp = (uint2*)(out + (size_t)row * D_);
    #pragma unroll
    for (int k = 0; k < 6; k++) {
        const int i4 = lane + 32 * k;
        float4 gg = gv[i4], bb = bv[i4];
        float o0 = v[k].x * rs * gg.x + bb.x;
        float o1 = v[k].y * rs * gg.y + bb.y;
        float o2 = v[k].z * rs * gg.z + bb.z;
        float o3 = v[k].w * rs * gg.w + bb.w;
        hp[i4] = make_uint2(pack_f16x2(o0, o1), pack_f16x2(o2, o3));
    }
}

// ---------------- fused prep: wcast x3 + LN1 in one launch -------------------
#define WQ_NB  ((D3_ / 32) * (D_ / 32))    /* 72*24 = 1728 */
#define W1_NB  ((DFF_ / 32) * (D_ / 32))   /* 96*24 = 2304 */
#define W2_NB  ((D_ / 32) * (DFF_ / 32))   /* 24*96 = 2304 */
#define LN_NB  (NTOK / 8)                  /* 1024 */
#define PREP_NB (WQ_NB + W1_NB + W2_NB + LN_NB)  /* 7360 */

__global__ void __launch_bounds__(256) prep_kernel(
    const float* __restrict__ w_qkv, const float* __restrict__ w1,
    const float* __restrict__ w2,
    const float* __restrict__ x, const float* __restrict__ ln1_g,
    const float* __restrict__ ln1_b,
    __half* __restrict__ wq, __half* __restrict__ w1t,
    __half* __restrict__ w2t, __half* __restrict__ h)
{
    int bid = blockIdx.x;
    if (bid < WQ_NB) {
        wcast_body(w_qkv, wq, D_, D3_, bid % (D3_ / 32), bid / (D3_ / 32));
        return;
    }
    bid -= WQ_NB;
    if (bid < W1_NB) {
        wcast_body(w1, w1t, D_, DFF_, bid % (DFF_ / 32), bid / (DFF_ / 32));
        return;
    }
    bid -= W1_NB;
    if (bid < W2_NB) {
        wcast_body(w2, w2t, DFF_, D_, bid % (D_ / 32), bid / (D_ / 32));
        return;
    }
    bid -= W2_NB;
    ln_body(x, ln1_g, ln1_b, h, bid);
}

// ---------------- standalone LN (for LN2) ------------------------------------
__global__ void __launch_bounds__(256) ln_f16_kernel(
    const float* __restrict__ x, const float* __restrict__ g,
    const float* __restrict__ b, __half* __restrict__ out)
{
    ln_body(x, g, b, out, blockIdx.x);
}

// ---------------- MMA GEMM: C[M,N] = A[M,K] @ B[N,K]^T, fp16 single-pass ----
// 128x128 tile, K chunk 64, 256 threads, 8 warps (4m x 2n), warp 32x64.
// cp.async 2-stage, 2 CTAs/SM.
// EPI: 1 bias+GELU->fp16 ; 2 bias,*0.9+res->fp32 ; 3 bias->fp16
#define BM   128
#define BN   128
#define BKC  64
#define ROWB 144          /* 64 fp16 = 128B + 16B pad */
#define TILEB (128 * ROWB)     /* 18432 */
#define STAGEB (2 * TILEB)     /* 36864 */
#define GEMM_SMEM (2 * STAGEB) /* 73728 */

template <int EPI>
__global__ void __launch_bounds__(256, 2) gemm_mma(
    const __half* __restrict__ A_g, const __half* __restrict__ B_g,
    const float* __restrict__ bias, const float* __restrict__ res,
    float* __restrict__ Cf, __half* __restrict__ Ch,
    int M, int N, int K)
{
    extern __shared__ char dsm[];
    const uint32_t sbase = smem_u32(dsm);

    const int tid  = threadIdx.x;
    const int lane = tid & 31;
    const int wid  = tid >> 5;
    const int wm   = wid & 3;
    const int wn   = wid >> 2;
    const int m0   = blockIdx.y * BM;
    const int n0   = blockIdx.x * BN;

    const int a_row = lane & 15;
    const int a_col = (lane >> 4) << 3;
    const uint32_t offA = (uint32_t)((wm * 32 + a_row) * ROWB + a_col * 2);
    const int b_row = (lane & 7) | ((lane >> 4) << 3);
    const int b_col = ((lane >> 3) & 1) << 3;
    const uint32_t offB = (uint32_t)(TILEB + (wn * 64 + b_row) * ROWB + b_col * 2);

    float acc[2][8][4];
    #pragma unroll
    for (int i = 0; i < 2; i++)
        #pragma unroll
        for (int j = 0; j < 8; j++)
            #pragma unroll
            for (int k = 0; k < 4; k++) acc[i][j][k] = 0.f;

    const int ldu = K >> 3;
    const uint4* ga = (const uint4*)A_g;
    const uint4* gb = (const uint4*)B_g;

    const int nchunks = K / BKC;

    auto issue = [&](int stage, int ch) {
        const int k0u = ch * (BKC / 8);
        const uint32_t so = sbase + (uint32_t)stage * STAGEB;
        #pragma unroll
        for (int i = 0; i < 4; i++) {
            const int idx = tid + i * 256;
            const int r = idx >> 3, q = idx & 7;
            const uint32_t d = so + (uint32_t)(r * ROWB + q * 16);
            cp_async16(d,         ga + (size_t)(m0 + r) * ldu + k0u + q);
            cp_async16(d + TILEB, gb + (size_t)(n0 + r) * ldu + k0u + q);
        }
    };

    issue(0, 0);
    CP_COMMIT();

    for (int ch = 0; ch < nchunks; ch++) {
        if (ch + 1 < nchunks) {
            issue((ch + 1) & 1, ch + 1);
            CP_COMMIT();
            CP_WAIT(1);
        } else {
            CP_WAIT(0);
        }
        __syncthreads();

        const uint32_t st = sbase + (uint32_t)(ch & 1) * STAGEB;
        const uint32_t aT = st + offA;
        const uint32_t bT = st + offB;

        #pragma unroll
        for (int ks = 0; ks < BKC; ks += 16) {
            uint32_t ah[2][4];
            #pragma unroll
            for (int mt = 0; mt < 2; mt++)
                ldsm_x4(ah[mt], aT + mt * (16 * ROWB) + ks * 2);
            #pragma unroll
            for (int np = 0; np < 4; np++) {
                uint32_t bh[4];
                ldsm_x4(bh, bT + np * (16 * ROWB) + ks * 2);
                #pragma unroll
                for (int mt = 0; mt < 2; mt++) {
                    mma16816(acc[mt][2 * np],     ah[mt], bh[0], bh[1]);
                    mma16816(acc[mt][2 * np + 1], ah[mt], bh[2], bh[3]);
                }
            }
        }
        __syncthreads();
    }

    // epilogue
    const int lr = lane >> 2;
    const int lc = (lane & 3) * 2;
    #pragma unroll
    for (int mt = 0; mt < 2; mt++) {
        #pragma unroll
        for (int nt = 0; nt < 8; nt++) {
            #pragma unroll
            for (int hh = 0; hh < 2; hh++) {
                const int gr = m0 + wm * 32 + mt * 16 + lr + hh * 8;
                const int gc = n0 + wn * 64 + nt * 8 + lc;
                float v0 = acc[mt][nt][hh * 2 + 0] + bias[gc];
                float v1 = acc[mt][nt][hh * 2 + 1] + bias[gc + 1];
                const size_t go = (size_t)gr * N + gc;
                if (EPI == 1) {
                    v0 = 0.5f * v0 * (1.0f + erff(v0 * 0.70710678118654752f));
                    v1 = 0.5f * v1 * (1.0f + erff(v1 * 0.70710678118654752f));
                    ((uint32_t*)Ch)[go >> 1] = pack_f16x2(v0, v1);
                } else if (EPI == 2) {
                    float2 rr = *(const float2*)&res[go];
                    float2 o2 = make_float2(v0 * SURV_ + rr.x, v1 * SURV_ + rr.y);
                    *(float2*)&Cf[go] = o2;
                } else {  // EPI == 3
                    ((uint32_t*)Ch)[go >> 1] = pack_f16x2(v0, v1);
                }
            }
        }
    }
}

// ---------------- Flash attention (R10 champion config) ----------------------
#define FQT 64
#define KT  64
#define QB_  9216                  /* 64 rows * 144B */
#define KB_  9216
#define FLASH_SMEM (QB_ + 4 * KB_) /* 46080 */

__global__ void __launch_bounds__(128) flash_mma(
    const __half* __restrict__ qkv, const float* __restrict__ x,
    float* __restrict__ x1)
{
    extern __shared__ char fsm[];
    const uint32_t sb = smem_u32(fsm);

    const int t = threadIdx.x;
    const int lane = t & 31, wid = t >> 5;
    const int qt = blockIdx.x, h = blockIdx.y, b = blockIdx.z;
    const size_t base = (size_t)b * P_ * D3_;
    const int q0 = qt * FQT, hc = h * 64;

    #pragma unroll
    for (int i = 0; i < 4; i++) {
        int idx = t + i * 128;
        int r = idx >> 3, c8 = (idx & 7) << 3;
        *(uint4*)(fsm + r * 144 + c8 * 2) =
            *(const uint4*)(qkv + base + (size_t)(q0 + r) * D3_ + hc + c8);
    }

    auto issueKV = [&](int stage, int kt) {
        const int k0 = kt * KT;
        const uint32_t kb = sb + QB_ + (uint32_t)stage * KB_;
        const uint32_t vb = sb + QB_ + 2 * KB_ + (uint32_t)stage * KB_;
        #pragma unroll
        for (int i = 0; i < 4; i++) {
            int idx = t + i * 128;
            int r = idx >> 3, c8 = (idx & 7) << 3;
            cp_async16(kb + r * 144 + c8 * 2,
                       qkv + base + (size_t)(k0 + r) * D3_ + D_ + hc + c8);
            cp_async16(vb + r * 144 + c8 * 2,
                       qkv + base + (size_t)(k0 + r) * D3_ + 2 * D_ + hc + c8);
        }
    };

    issueKV(0, 0);
    CP_COMMIT();
    __syncthreads();

    uint32_t qf[4][4];
    {
        const int qr = lane & 15;
        const int qc = (lane >> 4) << 3;
        #pragma unroll
        for (int ks = 0; ks < 4; ks++)
            ldsm_x4(qf[ks], sb + (wid * 16 + qr) * 144 + (ks * 16 + qc) * 2);
    }

    float mrow[2] = {-1e30f, -1e30f};
    float lrow[2] = {0.f, 0.f};
    float o[8][4];
    #pragma unroll
    for (int i = 0; i < 8; i++)
        #pragma unroll
        for (int j = 0; j < 4; j++) o[i][j] = 0.f;

    const float SCL = 0.18033688011112042f;  // (1/8) * log2(e)

    const int krow = (lane & 7) + ((lane >> 4) << 3);
    const int kcol = ((lane >> 3) & 1) << 3;
    const int vrow = (lane & 7) + (((lane >> 3) & 1) << 3);
    const int vcol = (lane >> 4) << 3;

    const int niter = P_ / KT;
    for (int kt = 0; kt < niter; kt++) {
        if (kt + 1 < niter) {
            issueKV((kt + 1) & 1, kt + 1);
            CP_COMMIT();
            CP_WAIT(1);
        } else {
            CP_WAIT(0);
        }
        __syncthreads();

        const uint32_t kst = sb + QB_ + (uint32_t)(kt & 1) * KB_;
        const uint32_t vst = sb + QB_ + 2 * KB_ + (uint32_t)(kt & 1) * KB_;

        float s[8][4];
        #pragma unroll
        for (int i = 0; i < 8; i++)
            #pragma unroll
            for (int j = 0; j < 4; j++) s[i][j] = 0.f;
        #pragma unroll
        for (int ks = 0; ks < 4; ks++) {
            #pragma unroll
            for (int tp = 0; tp < 4; tp++) {
                uint32_t kf[4];
                ldsm_x4(kf, kst + (tp * 16 + krow) * 144 + (ks * 16 + kcol) * 2);
                mma16816(s[2 * tp],     qf[ks], kf[0], kf[1]);
                mma16816(s[2 * tp + 1], qf[ks], kf[2], kf[3]);
            }
        }

        float pm0 = -1e30f, pm1 = -1e30f;
        #pragma unroll
        for (int nt = 0; nt < 8; nt++) {
            pm0 = fmaxf(pm0, fmaxf(s[nt][0], s[nt][1]));
            pm1 = fmaxf(pm1, fmaxf(s[nt][2], s[nt][3]));
        }
        pm0 = fmaxf(pm0, __shfl_xor_sync(0xffffffffu, pm0, 1));
        pm0 = fmaxf(pm0, __shfl_xor_sync(0xffffffffu, pm0, 2));
        pm1 = fmaxf(pm1, __shfl_xor_sync(0xffffffffu, pm1, 1));
        pm1 = fmaxf(pm1, __shfl_xor_sync(0xffffffffu, pm1, 2));
        const float mn0 = fmaxf(mrow[0], pm0);
        const float mn1 = fmaxf(mrow[1], pm1);
        const float f0 = ex2f((mrow[0] - mn0) * SCL);
        const float f1 = ex2f((mrow[1] - mn1) * SCL);

        uint32_t pf[4][4];
        #pragma unroll
        for (int ks = 0; ks < 4; ks++) {
            pf[ks][0] = h2ex2(pack_f16x2((s[2 * ks][0] - mn0) * SCL,
                                         (s[2 * ks][1] - mn0) * SCL));
            pf[ks][1] = h2ex2(pack_f16x2((s[2 * ks][2] - mn1) * SCL,
                                         (s[2 * ks][3] - mn1) * SCL));
            pf[ks][2] = h2ex2(pack_f16x2((s[2 * ks + 1][0] - mn0) * SCL,
                                         (s[2 * ks + 1][1] - mn0) * SCL));
            pf[ks][3] = h2ex2(pack_f16x2((s[2 * ks + 1][2] - mn1) * SCL,
                                         (s[2 * ks + 1][3] - mn1) * SCL));
        }

        // row sums via ones-MMA (la[0]=row lr, la[2]=row lr+8)
        float la[4] = {0.f, 0.f, 0.f, 0.f};
        #pragma unroll
        for (int ks = 0; ks < 4; ks++)
            mma16816(la, pf[ks], ONES2, ONES2);

        lrow[0] = lrow[0] * f0 + la[0];
        lrow[1] = lrow[1] * f1 + la[2];
        mrow[0] = mn0;
        mrow[1] = mn1;

        #pragma unroll
        for (int nt = 0; nt < 8; nt++) {
            o[nt][0] *= f0; o[nt][1] *= f0;
            o[nt][2] *= f1; o[nt][3] *= f1;
        }

        #pragma unroll
        for (int ks = 0; ks < 4; ks++) {
            #pragma unroll
            for (int tp = 0; tp < 4; tp++) {
                uint32_t vf[4];
                ldsm_x4_t(vf, vst + (ks * 16 + vrow) * 144 + (tp * 16 + vcol) * 2);
                mma16816(o[2 * tp],     pf[ks], vf[0], vf[1]);
                mma16816(o[2 * tp + 1], pf[ks], vf[2], vf[3]);
            }
        }
        __syncthreads();
    }

    const float inv0 = 1.0f / lrow[0];
    const float inv1 = 1.0f / lrow[1];
    const int r0 = q0 + wid * 16 + (lane >> 2);
    const size_t row0 = ((size_t)b * P_ + r0) * D_ + hc + (lane & 3) * 2;
    const size_t row1 = row0 + 8 * D_;
    #pragma unroll
    for (int nt = 0; nt < 8; nt++) {
        float2 xa = *(const float2*)&x[row0 + nt * 8];
        float2 ra;
        ra.x = o[nt][0] * inv0 * SURV_ + xa.x;
        ra.y = o[nt][1] * inv0 * SURV_ + xa.y;
        *(float2*)&x1[row0 + nt * 8] = ra;
        float2 xb = *(const float2*)&x[row1 + nt * 8];
        float2 rb;
        rb.x = o[nt][2] * inv1 * SURV_ + xb.x;
        rb.y = o[nt][3] * inv1 * SURV_ + xb.y;
        *(float2*)&x1[row1 + nt * 8] = rb;
    }
}

// ---------------- launch ----------------------------------------------------
extern "C" void kernel_launch(void* const* d_in, const int* in_sizes, int n_in,
                              void* d_out, int out_size)
{
    const float* x     = (const float*)d_in[0];
    const float* ln1_g = (const float*)d_in[1];
    const float* ln1_b = (const float*)d_in[2];
    const float* w_qkv = (const float*)d_in[3];
    const float* b_qkv = (const float*)d_in[4];
    const float* ln2_g = (const float*)d_in[5];
    const float* ln2_b = (const float*)d_in[6];
    const float* w1    = (const float*)d_in[7];
    const float* b1    = (const float*)d_in[8];
    const float* w2    = (const float*)d_in[9];
    const float* b2    = (const float*)d_in[10];
    float* out = (float*)d_out;

    __half *h, *qkvh, *ffn, *wq, *w1t, *w2t;
    float *x1;
    cudaGetSymbolAddress((void**)&h,    g_h);
    cudaGetSymbolAddress((void**)&qkvh, g_qkvh);
    cudaGetSymbolAddress((void**)&x1,   g_x1);
    cudaGetSymbolAddress((void**)&ffn,  g_ffn);
    cudaGetSymbolAddress((void**)&wq,   g_wq);
    cudaGetSymbolAddress((void**)&w1t,  g_w1);
    cudaGetSymbolAddress((void**)&w2t,  g_w2);

    cudaFuncSetAttribute(gemm_mma<1>,
                         cudaFuncAttributeMaxDynamicSharedMemorySize, GEMM_SMEM);
    cudaFuncSetAttribute(gemm_mma<2>,
                         cudaFuncAttributeMaxDynamicSharedMemorySize, GEMM_SMEM);
    cudaFuncSetAttribute(gemm_mma<3>,
                         cudaFuncAttributeMaxDynamicSharedMemorySize, GEMM_SMEM);
    cudaFuncSetAttribute(flash_mma,
                         cudaFuncAttributeMaxDynamicSharedMemorySize, FLASH_SMEM);

    // 0) fused prep: weight transpose+cast x3 + LN1, one launch
    prep_kernel<<<PREP_NB, 256>>>(w_qkv, w1, w2, x, ln1_g, ln1_b,
                                  wq, w1t, w2t, h);
    // 1) QKV projection -> fp16
    gemm_mma<3><<<dim3(D3_ / BN, NTOK / BM), 256, GEMM_SMEM>>>(
        h, wq, b_qkv, nullptr, nullptr, qkvh, NTOK, D3_, D_);
    // 2) attention + residual -> x1
    flash_mma<<<dim3(P_ / FQT, H_, B_), 128, FLASH_SMEM>>>(qkvh, x, x1);
    // 3) LN2 -> fp16
    ln_f16_kernel<<<NTOK / 8, 256>>>(x1, ln2_g, ln2_b, h);
    // 4) MLP up + GELU -> fp16
    gemm_mma<1><<<dim3(DFF_ / BN, NTOK / BM), 256, GEMM_SMEM>>>(
        h, w1t, b1, nullptr, nullptr, ffn, NTOK, DFF_, D_);
    // 5) MLP down + droppath + residual -> out
    gemm_mma<2><<<dim3(D_ / BN, NTOK / BM), 256, GEMM_SMEM>>>(
        ffn, w2t, b2, x1, out, nullptr, NTOK, D_, DFF_);
}

// round 16
// speedup vs baseline: 1.0523x; 1.0298x over previous
#include <cuda_runtime.h>
#include <cuda_fp16.h>
#include <math.h>
#include <stdint.h>

#define D_    768
#define P_    2048
#define B_    4
#define H_    12
#define DFF_  3072
#define NTOK  (B_ * P_)      /* 8192 */
#define D3_   (3 * D_)       /* 2304 */
#define EPS_  1e-3f
#define SURV_ 0.9f

// ---------------- scratch (static device globals) ---------------------------
__device__ __half g_h   [NTOK * D_];     // LN output, fp16
__device__ __half g_qkvh[NTOK * D3_];    // fp16 QKV
__device__ float  g_x1  [NTOK * D_];
__device__ __half g_ffn [NTOK * DFF_];   // MLP hidden, fp16
// transposed weights: [N, K] layout, fp16
__device__ __half g_wq[D3_ * D_];
__device__ __half g_w1[DFF_ * D_];
__device__ __half g_w2[D_ * DFF_];

// ---------------- helpers ----------------------------------------------------
__device__ __forceinline__ uint32_t smem_u32(const void* p) {
    uint32_t a;
    asm("{ .reg .u64 t; cvta.to.shared.u64 t, %1; cvt.u32.u64 %0, t; }"
        : "=r"(a) : "l"(p));
    return a;
}
__device__ __forceinline__ void ldsm_x4(uint32_t* r, uint32_t addr) {
    asm volatile("ldmatrix.sync.aligned.m8n8.x4.shared.b16 {%0,%1,%2,%3}, [%4];"
                 : "=r"(r[0]), "=r"(r[1]), "=r"(r[2]), "=r"(r[3]) : "r"(addr));
}
__device__ __forceinline__ void ldsm_x4_t(uint32_t* r, uint32_t addr) {
    asm volatile("ldmatrix.sync.aligned.m8n8.x4.trans.shared.b16 {%0,%1,%2,%3}, [%4];"
                 : "=r"(r[0]), "=r"(r[1]), "=r"(r[2]), "=r"(r[3]) : "r"(addr));
}
__device__ __forceinline__ void mma16816(float* c, const uint32_t* a,
                                         uint32_t b0, uint32_t b1) {
    asm volatile(
        "mma.sync.aligned.m16n8k16.row.col.f32.f16.f16.f32 "
        "{%0,%1,%2,%3}, {%4,%5,%6,%7}, {%8,%9}, {%0,%1,%2,%3};"
        : "+f"(c[0]), "+f"(c[1]), "+f"(c[2]), "+f"(c[3])
        : "r"(a[0]), "r"(a[1]), "r"(a[2]), "r"(a[3]), "r"(b0), "r"(b1));
}
__device__ __forceinline__ float ex2f(float x) {
    float y; asm("ex2.approx.f32 %0, %1;" : "=f"(y) : "f"(x)); return y;
}
__device__ __forceinline__ uint32_t h2ex2(uint32_t a) {
    uint32_t d; asm("ex2.approx.f16x2 %0, %1;" : "=r"(d) : "r"(a)); return d;
}
__device__ __forceinline__ float tanhfast(float x) {
    float y; asm("tanh.approx.f32 %0, %1;" : "=f"(y) : "f"(x)); return y;
}
// tanh-form GELU with HW tanh (max abs dev from exact GELU ~3e-4)
__device__ __forceinline__ float gelu_fast(float v) {
    float u = 0.7978845608028654f * (v + 0.044715f * v * v * v);
    return 0.5f * v * (1.0f + tanhfast(u));
}
// packed fp16x2 = {lo half: first arg, hi half: second arg}
__device__ __forceinline__ uint32_t pack_f16x2(float lo, float hi) {
    uint32_t d;
    asm("cvt.rn.f16x2.f32 %0, %1, %2;" : "=r"(d) : "f"(hi), "f"(lo));
    return d;
}
__device__ __forceinline__ void cp_async16(uint32_t dst, const void* src) {
    asm volatile("cp.async.cg.shared.global [%0], [%1], 16;"
                 :: "r"(dst), "l"(src));
}
#define CP_COMMIT() asm volatile("cp.async.commit_group;" ::: "memory")
#define CP_WAIT(n)  asm volatile("cp.async.wait_group %0;" :: "n"(n) : "memory")
#define ONES2 0x3C003C00u   /* fp16x2 {1.0, 1.0} */

// ---------------- prep bodies (identical math to proven kernels) -------------
__device__ __forceinline__ void wcast_body(
    const float* __restrict__ w, __half* __restrict__ wt,
    int K, int N, int bx, int by)
{
    __shared__ float t[32][33];
    const int n0 = bx * 32, k0 = by * 32;
    const int tx = threadIdx.x & 31, ty = threadIdx.x >> 5;
    #pragma unroll
    for (int j = 0; j < 4; j++) {
        int k = ty + j * 8;
        t[k][tx] = w[(size_t)(k0 + k) * N + n0 + tx];
    }
    __syncthreads();
    #pragma unroll
    for (int j = 0; j < 4; j++) {
        int n = ty + j * 8;
        wt[(size_t)(n0 + n) * K + k0 + tx] = __float2half(t[tx][n]);
    }
}

__device__ __forceinline__ void ln_body(
    const float* __restrict__ x, const float* __restrict__ g,
    const float* __restrict__ b, __half* __restrict__ out, int blk)
{
    const int row  = blk * 8 + (threadIdx.x >> 5);
    const int lane = threadIdx.x & 31;
    const float4* xr = (const float4*)(x + (size_t)row * D_);
    const float4* gv = (const float4*)g;
    const float4* bv = (const float4*)b;

    float4 v[6];
    float s = 0.f;
    #pragma unroll
    for (int k = 0; k < 6; k++) {
        v[k] = xr[lane + 32 * k];
        s += v[k].x + v[k].y + v[k].z + v[k].w;
    }
    #pragma unroll
    for (int o = 16; o; o >>= 1) s += __shfl_xor_sync(0xffffffffu, s, o);
    const float mu = s * (1.0f / D_);

    float q = 0.f;
    #pragma unroll
    for (int k = 0; k < 6; k++) {
        v[k].x -= mu; v[k].y -= mu; v[k].z -= mu; v[k].w -= mu;
        q += v[k].x * v[k].x + v[k].y * v[k].y + v[k].z * v[k].z + v[k].w * v[k].w;
    }
    #pragma unroll
    for (int o = 16; o; o >>= 1) q += __shfl_xor_sync(0xffffffffu, q, o);
    const float rs = rsqrtf(q * (1.0f / D_) + EPS_);

    uint2* hp = (uint2*)(out + (size_t)row * D_);
    #pragma unroll
    for (int k = 0; k < 6; k++) {
        const int i4 = lane + 32 * k;
        float4 gg = gv[i4], bb = bv[i4];
        float o0 = v[k].x * rs * gg.x + bb.x;
        float o1 = v[k].y * rs * gg.y + bb.y;
        float o2 = v[k].z * rs * gg.z + bb.z;
        float o3 = v[k].w * rs * gg.w + bb.w;
        hp[i4] = make_uint2(pack_f16x2(o0, o1), pack_f16x2(o2, o3));
    }
}

// ---------------- fused prep: wcast x3 + LN1 in one launch -------------------
#define WQ_NB  ((D3_ / 32) * (D_ / 32))    /* 1728 */
#define W1_NB  ((DFF_ / 32) * (D_ / 32))   /* 2304 */
#define W2_NB  ((D_ / 32) * (DFF_ / 32))   /* 2304 */
#define LN_NB  (NTOK / 8)                  /* 1024 */
#define PREP_NB (WQ_NB + W1_NB + W2_NB + LN_NB)  /* 7360 */

__global__ void __launch_bounds__(256) prep_kernel(
    const float* __restrict__ w_qkv, const float* __restrict__ w1,
    const float* __restrict__ w2,
    const float* __restrict__ x, const float* __restrict__ ln1_g,
    const float* __restrict__ ln1_b,
    __half* __restrict__ wq, __half* __restrict__ w1t,
    __half* __restrict__ w2t, __half* __restrict__ h)
{
    int bid = blockIdx.x;
    if (bid < WQ_NB) {
        wcast_body(w_qkv, wq, D_, D3_, bid % (D3_ / 32), bid / (D3_ / 32));
        return;
    }
    bid -= WQ_NB;
    if (bid < W1_NB) {
        wcast_body(w1, w1t, D_, DFF_, bid % (DFF_ / 32), bid / (DFF_ / 32));
        return;
    }
    bid -= W1_NB;
    if (bid < W2_NB) {
        wcast_body(w2, w2t, DFF_, D_, bid % (D_ / 32), bid / (D_ / 32));
        return;
    }
    bid -= W2_NB;
    ln_body(x, ln1_g, ln1_b, h, bid);
}

// ---------------- standalone LN (for LN2) ------------------------------------
__global__ void __launch_bounds__(256) ln_f16_kernel(
    const float* __restrict__ x, const float* __restrict__ g,
    const float* __restrict__ b, __half* __restrict__ out)
{
    ln_body(x, g, b, out, blockIdx.x);
}

// ---------------- MMA GEMM: C[M,N] = A[M,K] @ B[N,K]^T, fp16 single-pass ----
// 128x128 tile, K chunk 64, 256 threads, 8 warps (4m x 2n), warp 32x64.
// cp.async 2-stage, 2 CTAs/SM.
// EPI: 1 bias+GELU->fp16 ; 2 bias,*0.9+res->fp32 ; 3 bias->fp16
#define BM   128
#define BN   128
#define BKC  64
#define ROWB 144          /* 64 fp16 = 128B + 16B pad */
#define TILEB (128 * ROWB)     /* 18432 */
#define STAGEB (2 * TILEB)     /* 36864 */
#define GEMM_SMEM (2 * STAGEB) /* 73728 */

template <int EPI>
__global__ void __launch_bounds__(256, 2) gemm_mma(
    const __half* __restrict__ A_g, const __half* __restrict__ B_g,
    const float* __restrict__ bias, const float* __restrict__ res,
    float* __restrict__ Cf, __half* __restrict__ Ch,
    int M, int N, int K)
{
    extern __shared__ char dsm[];
    const uint32_t sbase = smem_u32(dsm);

    const int tid  = threadIdx.x;
    const int lane = tid & 31;
    const int wid  = tid >> 5;
    const int wm   = wid & 3;
    const int wn   = wid >> 2;
    const int m0   = blockIdx.y * BM;
    const int n0   = blockIdx.x * BN;

    const int a_row = lane & 15;
    const int a_col = (lane >> 4) << 3;
    const uint32_t offA = (uint32_t)((wm * 32 + a_row) * ROWB + a_col * 2);
    const int b_row = (lane & 7) | ((lane >> 4) << 3);
    const int b_col = ((lane >> 3) & 1) << 3;
    const uint32_t offB = (uint32_t)(TILEB + (wn * 64 + b_row) * ROWB + b_col * 2);

    float acc[2][8][4];
    #pragma unroll
    for (int i = 0; i < 2; i++)
        #pragma unroll
        for (int j = 0; j < 8; j++)
            #pragma unroll
            for (int k = 0; k < 4; k++) acc[i][j][k] = 0.f;

    const int ldu = K >> 3;
    const uint4* ga = (const uint4*)A_g;
    const uint4* gb = (const uint4*)B_g;

    const int nchunks = K / BKC;

    auto issue = [&](int stage, int ch) {
        const int k0u = ch * (BKC / 8);
        const uint32_t so = sbase + (uint32_t)stage * STAGEB;
        #pragma unroll
        for (int i = 0; i < 4; i++) {
            const int idx = tid + i * 256;
            const int r = idx >> 3, q = idx & 7;
            const uint32_t d = so + (uint32_t)(r * ROWB + q * 16);
            cp_async16(d,         ga + (size_t)(m0 + r) * ldu + k0u + q);
            cp_async16(d + TILEB, gb + (size_t)(n0 + r) * ldu + k0u + q);
        }
    };

    issue(0, 0);
    CP_COMMIT();

    for (int ch = 0; ch < nchunks; ch++) {
        if (ch + 1 < nchunks) {
            issue((ch + 1) & 1, ch + 1);
            CP_COMMIT();
            CP_WAIT(1);
        } else {
            CP_WAIT(0);
        }
        __syncthreads();

        const uint32_t st = sbase + (uint32_t)(ch & 1) * STAGEB;
        const uint32_t aT = st + offA;
        const uint32_t bT = st + offB;

        #pragma unroll
        for (int ks = 0; ks < BKC; ks += 16) {
            uint32_t ah[2][4];
            #pragma unroll
            for (int mt = 0; mt < 2; mt++)
                ldsm_x4(ah[mt], aT + mt * (16 * ROWB) + ks * 2);
            #pragma unroll
            for (int np = 0; np < 4; np++) {
                uint32_t bh[4];
                ldsm_x4(bh, bT + np * (16 * ROWB) + ks * 2);
                #pragma unroll
                for (int mt = 0; mt < 2; mt++) {
                    mma16816(acc[mt][2 * np],     ah[mt], bh[0], bh[1]);
                    mma16816(acc[mt][2 * np + 1], ah[mt], bh[2], bh[3]);
                }
            }
        }
        __syncthreads();
    }

    // epilogue
    const int lr = lane >> 2;
    const int lc = (lane & 3) * 2;
    #pragma unroll
    for (int mt = 0; mt < 2; mt++) {
        #pragma unroll
        for (int nt = 0; nt < 8; nt++) {
            #pragma unroll
            for (int hh = 0; hh < 2; hh++) {
                const int gr = m0 + wm * 32 + mt * 16 + lr + hh * 8;
                const int gc = n0 + wn * 64 + nt * 8 + lc;
                float v0 = acc[mt][nt][hh * 2 + 0] + bias[gc];
                float v1 = acc[mt][nt][hh * 2 + 1] + bias[gc + 1];
                const size_t go = (size_t)gr * N + gc;
                if (EPI == 1) {
                    v0 = gelu_fast(v0);
                    v1 = gelu_fast(v1);
                    ((uint32_t*)Ch)[go >> 1] = pack_f16x2(v0, v1);
                } else if (EPI == 2) {
                    float2 rr = *(const float2*)&res[go];
                    float2 o2 = make_float2(v0 * SURV_ + rr.x, v1 * SURV_ + rr.y);
                    *(float2*)&Cf[go] = o2;
                } else {  // EPI == 3
                    ((uint32_t*)Ch)[go >> 1] = pack_f16x2(v0, v1);
                }
            }
        }
    }
}

// ---------------- Flash attention (R10 champion config) ----------------------
#define FQT 64
#define KT  64
#define QB_  9216                  /* 64 rows * 144B */
#define KB_  9216
#define FLASH_SMEM (QB_ + 4 * KB_) /* 46080 */

__global__ void __launch_bounds__(128) flash_mma(
    const __half* __restrict__ qkv, const float* __restrict__ x,
    float* __restrict__ x1)
{
    extern __shared__ char fsm[];
    const uint32_t sb = smem_u32(fsm);

    const int t = threadIdx.x;
    const int lane = t & 31, wid = t >> 5;
    const int qt = blockIdx.x, h = blockIdx.y, b = blockIdx.z;
    const size_t base = (size_t)b * P_ * D3_;
    const int q0 = qt * FQT, hc = h * 64;

    #pragma unroll
    for (int i = 0; i < 4; i++) {
        int idx = t + i * 128;
        int r = idx >> 3, c8 = (idx & 7) << 3;
        *(uint4*)(fsm + r * 144 + c8 * 2) =
            *(const uint4*)(qkv + base + (size_t)(q0 + r) * D3_ + hc + c8);
    }

    auto issueKV = [&](int stage, int kt) {
        const int k0 = kt * KT;
        const uint32_t kb = sb + QB_ + (uint32_t)stage * KB_;
        const uint32_t vb = sb + QB_ + 2 * KB_ + (uint32_t)stage * KB_;
        #pragma unroll
        for (int i = 0; i < 4; i++) {
            int idx = t + i * 128;
            int r = idx >> 3, c8 = (idx & 7) << 3;
            cp_async16(kb + r * 144 + c8 * 2,
                       qkv + base + (size_t)(k0 + r) * D3_ + D_ + hc + c8);
            cp_async16(vb + r * 144 + c8 * 2,
                       qkv + base + (size_t)(k0 + r) * D3_ + 2 * D_ + hc + c8);
        }
    };

    issueKV(0, 0);
    CP_COMMIT();
    __syncthreads();

    uint32_t qf[4][4];
    {
        const int qr = lane & 15;
        const int qc = (lane >> 4) << 3;
        #pragma unroll
        for (int ks = 0; ks < 4; ks++)
            ldsm_x4(qf[ks], sb + (wid * 16 + qr) * 144 + (ks * 16 + qc) * 2);
    }

    float mrow[2] = {-1e30f, -1e30f};
    float lrow[2] = {0.f, 0.f};
    float o[8][4];
    #pragma unroll
    for (int i = 0; i < 8; i++)
        #pragma unroll
        for (int j = 0; j < 4; j++) o[i][j] = 0.f;

    const float SCL = 0.18033688011112042f;  // (1/8) * log2(e)

    const int krow = (lane & 7) + ((lane >> 4) << 3);
    const int kcol = ((lane >> 3) & 1) << 3;
    const int vrow = (lane & 7) + (((lane >> 3) & 1) << 3);
    const int vcol = (lane >> 4) << 3;

    const int niter = P_ / KT;
    for (int kt = 0; kt < niter; kt++) {
        if (kt + 1 < niter) {
            issueKV((kt + 1) & 1, kt + 1);
            CP_COMMIT();
            CP_WAIT(1);
        } else {
            CP_WAIT(0);
        }
        __syncthreads();

        const uint32_t kst = sb + QB_ + (uint32_t)(kt & 1) * KB_;
        const uint32_t vst = sb + QB_ + 2 * KB_ + (uint32_t)(kt & 1) * KB_;

        float s[8][4];
        #pragma unroll
        for (int i = 0; i < 8; i++)
            #pragma unroll
            for (int j = 0; j < 4; j++) s[i][j] = 0.f;
        #pragma unroll
        for (int ks = 0; ks < 4; ks++) {
            #pragma unroll
            for (int tp = 0; tp < 4; tp++) {
                uint32_t kf[4];
                ldsm_x4(kf, kst + (tp * 16 + krow) * 144 + (ks * 16 + kcol) * 2);
                mma16816(s[2 * tp],     qf[ks], kf[0], kf[1]);
                mma16816(s[2 * tp + 1], qf[ks], kf[2], kf[3]);
            }
        }

        float pm0 = -1e30f, pm1 = -1e30f;
        #pragma unroll
        for (int nt = 0; nt < 8; nt++) {
            pm0 = fmaxf(pm0, fmaxf(s[nt][0], s[nt][1]));
            pm1 = fmaxf(pm1, fmaxf(s[nt][2], s[nt][3]));
        }
        pm0 = fmaxf(pm0, __shfl_xor_sync(0xffffffffu, pm0, 1));
        pm0 = fmaxf(pm0, __shfl_xor_sync(0xffffffffu, pm0, 2));
        pm1 = fmaxf(pm1, __shfl_xor_sync(0xffffffffu, pm1, 1));
        pm1 = fmaxf(pm1, __shfl_xor_sync(0xffffffffu, pm1, 2));
        const float mn0 = fmaxf(mrow[0], pm0);
        const float mn1 = fmaxf(mrow[1], pm1);
        const float f0 = ex2f((mrow[0] - mn0) * SCL);
        const float f1 = ex2f((mrow[1] - mn1) * SCL);

        uint32_t pf[4][4];
        #pragma unroll
        for (int ks = 0; ks < 4; ks++) {
            pf[ks][0] = h2ex2(pack_f16x2((s[2 * ks][0] - mn0) * SCL,
                                         (s[2 * ks][1] - mn0) * SCL));
            pf[ks][1] = h2ex2(pack_f16x2((s[2 * ks][2] - mn1) * SCL,
                                         (s[2 * ks][3] - mn1) * SCL));
            pf[ks][2] = h2ex2(pack_f16x2((s[2 * ks + 1][0] - mn0) * SCL,
                                         (s[2 * ks + 1][1] - mn0) * SCL));
            pf[ks][3] = h2ex2(pack_f16x2((s[2 * ks + 1][2] - mn1) * SCL,
                                         (s[2 * ks + 1][3] - mn1) * SCL));
        }

        // row sums via ones-MMA (la[0]=row lr, la[2]=row lr+8)
        float la[4] = {0.f, 0.f, 0.f, 0.f};
        #pragma unroll
        for (int ks = 0; ks < 4; ks++)
            mma16816(la, pf[ks], ONES2, ONES2);

        lrow[0] = lrow[0] * f0 + la[0];
        lrow[1] = lrow[1] * f1 + la[2];
        mrow[0] = mn0;
        mrow[1] = mn1;

        #pragma unroll
        for (int nt = 0; nt < 8; nt++) {
            o[nt][0] *= f0; o[nt][1] *= f0;
            o[nt][2] *= f1; o[nt][3] *= f1;
        }

        #pragma unroll
        for (int ks = 0; ks < 4; ks++) {
            #pragma unroll
            for (int tp = 0; tp < 4; tp++) {
                uint32_t vf[4];
                ldsm_x4_t(vf, vst + (ks * 16 + vrow) * 144 + (tp * 16 + vcol) * 2);
                mma16816(o[2 * tp],     pf[ks], vf[0], vf[1]);
                mma16816(o[2 * tp + 1], pf[ks], vf[2], vf[3]);
            }
        }
        __syncthreads();
    }

    const float inv0 = 1.0f / lrow[0];
    const float inv1 = 1.0f / lrow[1];
    const int r0 = q0 + wid * 16 + (lane >> 2);
    const size_t row0 = ((size_t)b * P_ + r0) * D_ + hc + (lane & 3) * 2;
    const size_t row1 = row0 + 8 * D_;
    #pragma unroll
    for (int nt = 0; nt < 8; nt++) {
        float2 xa = *(const float2*)&x[row0 + nt * 8];
        float2 ra;
        ra.x = o[nt][0] * inv0 * SURV_ + xa.x;
        ra.y = o[nt][1] * inv0 * SURV_ + xa.y;
        *(float2*)&x1[row0 + nt * 8] = ra;
        float2 xb = *(const float2*)&x[row1 + nt * 8];
        float2 rb;
        rb.x = o[nt][2] * inv1 * SURV_ + xb.x;
        rb.y = o[nt][3] * inv1 * SURV_ + xb.y;
        *(float2*)&x1[row1 + nt * 8] = rb;
    }
}

// ---------------- launch ----------------------------------------------------
extern "C" void kernel_launch(void* const* d_in, const int* in_sizes, int n_in,
                              void* d_out, int out_size)
{
    const float* x     = (const float*)d_in[0];
    const float* ln1_g = (const float*)d_in[1];
    const float* ln1_b = (const float*)d_in[2];
    const float* w_qkv = (const float*)d_in[3];
    const float* b_qkv = (const float*)d_in[4];
    const float* ln2_g = (const float*)d_in[5];
    const float* ln2_b = (const float*)d_in[6];
    const float* w1    = (const float*)d_in[7];
    const float* b1    = (const float*)d_in[8];
    const float* w2    = (const float*)d_in[9];
    const float* b2    = (const float*)d_in[10];
    float* out = (float*)d_out;

    __half *h, *qkvh, *ffn, *wq, *w1t, *w2t;
    float *x1;
    cudaGetSymbolAddress((void**)&h,    g_h);
    cudaGetSymbolAddress((void**)&qkvh, g_qkvh);
    cudaGetSymbolAddress((void**)&x1,   g_x1);
    cudaGetSymbolAddress((void**)&ffn,  g_ffn);
    cudaGetSymbolAddress((void**)&wq,   g_wq);
    cudaGetSymbolAddress((void**)&w1t,  g_w1);
    cudaGetSymbolAddress((void**)&w2t,  g_w2);

    cudaFuncSetAttribute(gemm_mma<1>,
                         cudaFuncAttributeMaxDynamicSharedMemorySize, GEMM_SMEM);
    cudaFuncSetAttribute(gemm_mma<2>,
                         cudaFuncAttributeMaxDynamicSharedMemorySize, GEMM_SMEM);
    cudaFuncSetAttribute(gemm_mma<3>,
                         cudaFuncAttributeMaxDynamicSharedMemorySize, GEMM_SMEM);
    cudaFuncSetAttribute(flash_mma,
                         cudaFuncAttributeMaxDynamicSharedMemorySize, FLASH_SMEM);

    // 0) fused prep: weight transpose+cast x3 + LN1, one launch
    prep_kernel<<<PREP_NB, 256>>>(w_qkv, w1, w2, x, ln1_g, ln1_b,
                                  wq, w1t, w2t, h);
    // 1) QKV projection -> fp16
    gemm_mma<3><<<dim3(D3_ / BN, NTOK / BM), 256, GEMM_SMEM>>>(
        h, wq, b_qkv, nullptr, nullptr, qkvh, NTOK, D3_, D_);
    // 2) attention + residual -> x1
    flash_mma<<<dim3(P_ / FQT, H_, B_), 128, FLASH_SMEM>>>(qkvh, x, x1);
    // 3) LN2 -> fp16
    ln_f16_kernel<<<NTOK / 8, 256>>>(x1, ln2_g, ln2_b, h);
    // 4) MLP up + GELU -> fp16
    gemm_mma<1><<<dim3(DFF_ / BN, NTOK / BM), 256, GEMM_SMEM>>>(
        h, w1t, b1, nullptr, nullptr, ffn, NTOK, DFF_, D_);
    // 5) MLP down + droppath + residual -> out
    gemm_mma<2><<<dim3(D_ / BN, NTOK / BM), 256, GEMM_SMEM>>>(
        ffn, w2t, b2, x1, out, nullptr, NTOK, D_, DFF_);
}

// round 17
// speedup vs baseline: 1.0633x; 1.0105x over previous
#include <cuda_runtime.h>
#include <cuda_fp16.h>
#include <math.h>
#include <stdint.h>

#define D_    768
#define P_    2048
#define B_    4
#define H_    12
#define DFF_  3072
#define NTOK  (B_ * P_)      /* 8192 */
#define D3_   (3 * D_)       /* 2304 */
#define EPS_  1e-3f
#define SURV_ 0.9f

// ---------------- scratch (static device globals) ---------------------------
__device__ __half g_h   [NTOK * D_];     // LN output, fp16
__device__ __half g_qkvh[NTOK * D3_];    // fp16 QKV
__device__ float  g_x1  [NTOK * D_];
__device__ __half g_ffn [NTOK * DFF_];   // MLP hidden, fp16
// transposed weights: [N, K] layout, fp16
__device__ __half g_wq[D3_ * D_];
__device__ __half g_w1[DFF_ * D_];
__device__ __half g_w2[D_ * DFF_];

// ---------------- helpers ----------------------------------------------------
__device__ __forceinline__ uint32_t smem_u32(const void* p) {
    uint32_t a;
    asm("{ .reg .u64 t; cvta.to.shared.u64 t, %1; cvt.u32.u64 %0, t; }"
        : "=r"(a) : "l"(p));
    return a;
}
__device__ __forceinline__ void ldsm_x4(uint32_t* r, uint32_t addr) {
    asm volatile("ldmatrix.sync.aligned.m8n8.x4.shared.b16 {%0,%1,%2,%3}, [%4];"
                 : "=r"(r[0]), "=r"(r[1]), "=r"(r[2]), "=r"(r[3]) : "r"(addr));
}
__device__ __forceinline__ void ldsm_x4_t(uint32_t* r, uint32_t addr) {
    asm volatile("ldmatrix.sync.aligned.m8n8.x4.trans.shared.b16 {%0,%1,%2,%3}, [%4];"
                 : "=r"(r[0]), "=r"(r[1]), "=r"(r[2]), "=r"(r[3]) : "r"(addr));
}
__device__ __forceinline__ void mma16816(float* c, const uint32_t* a,
                                         uint32_t b0, uint32_t b1) {
    asm volatile(
        "mma.sync.aligned.m16n8k16.row.col.f32.f16.f16.f32 "
        "{%0,%1,%2,%3}, {%4,%5,%6,%7}, {%8,%9}, {%0,%1,%2,%3};"
        : "+f"(c[0]), "+f"(c[1]), "+f"(c[2]), "+f"(c[3])
        : "r"(a[0]), "r"(a[1]), "r"(a[2]), "r"(a[3]), "r"(b0), "r"(b1));
}
__device__ __forceinline__ float ex2f(float x) {
    float y; asm("ex2.approx.f32 %0, %1;" : "=f"(y) : "f"(x)); return y;
}
__device__ __forceinline__ uint32_t h2ex2(uint32_t a) {
    uint32_t d; asm("ex2.approx.f16x2 %0, %1;" : "=r"(d) : "r"(a)); return d;
}
__device__ __forceinline__ float tanhfast(float x) {
    float y; asm("tanh.approx.f32 %0, %1;" : "=f"(y) : "f"(x)); return y;
}
// tanh-form GELU with HW tanh (max abs dev from exact GELU ~3e-4)
__device__ __forceinline__ float gelu_fast(float v) {
    float u = 0.7978845608028654f * (v + 0.044715f * v * v * v);
    return 0.5f * v * (1.0f + tanhfast(u));
}
// packed fp16x2 = {lo half: first arg, hi half: second arg}
__device__ __forceinline__ uint32_t pack_f16x2(float lo, float hi) {
    uint32_t d;
    asm("cvt.rn.f16x2.f32 %0, %1, %2;" : "=r"(d) : "f"(hi), "f"(lo));
    return d;
}
__device__ __forceinline__ void cp_async16(uint32_t dst, const void* src) {
    asm volatile("cp.async.cg.shared.global [%0], [%1], 16;"
                 :: "r"(dst), "l"(src));
}
#define CP_COMMIT() asm volatile("cp.async.commit_group;" ::: "memory")
#define CP_WAIT(n)  asm volatile("cp.async.wait_group %0;" :: "n"(n) : "memory")
#define ONES2 0x3C003C00u   /* fp16x2 {1.0, 1.0} */

// ---------------- prep bodies (identical math to proven kernels) -------------
__device__ __forceinline__ void wcast_body(
    const float* __restrict__ w, __half* __restrict__ wt,
    int K, int N, int bx, int by)
{
    __shared__ float t[32][33];
    const int n0 = bx * 32, k0 = by * 32;
    const int tx = threadIdx.x & 31, ty = threadIdx.x >> 5;
    #pragma unroll
    for (int j = 0; j < 4; j++) {
        int k = ty + j * 8;
        t[k][tx] = w[(size_t)(k0 + k) * N + n0 + tx];
    }
    __syncthreads();
    #pragma unroll
    for (int j = 0; j < 4; j++) {
        int n = ty + j * 8;
        wt[(size_t)(n0 + n) * K + k0 + tx] = __float2half(t[tx][n]);
    }
}

__device__ __forceinline__ void ln_body(
    const float* __restrict__ x, const float* __restrict__ g,
    const float* __restrict__ b, __half* __restrict__ out, int blk)
{
    const int row  = blk * 8 + (threadIdx.x >> 5);
    const int lane = threadIdx.x & 31;
    const float4* xr = (const float4*)(x + (size_t)row * D_);
    const float4* gv = (const float4*)g;
    const float4* bv = (const float4*)b;

    float4 v[6];
    float s = 0.f;
    #pragma unroll
    for (int k = 0; k < 6; k++) {
        v[k] = xr[lane + 32 * k];
        s += v[k].x + v[k].y + v[k].z + v[k].w;
    }
    #pragma unroll
    for (int o = 16; o; o >>= 1) s += __shfl_xor_sync(0xffffffffu, s, o);
    const float mu = s * (1.0f / D_);

    float q = 0.f;
    #pragma unroll
    for (int k = 0; k < 6; k++) {
        v[k].x -= mu; v[k].y -= mu; v[k].z -= mu; v[k].w -= mu;
        q += v[k].x * v[k].x + v[k].y * v[k].y + v[k].z * v[k].z + v[k].w * v[k].w;
    }
    #pragma unroll
    for (int o = 16; o; o >>= 1) q += __shfl_xor_sync(0xffffffffu, q, o);
    const float rs = rsqrtf(q * (1.0f / D_) + EPS_);

    uint2* hp = (uint2*)(out + (size_t)row * D_);
    #pragma unroll
    for (int k = 0; k < 6; k++) {
        const int i4 = lane + 32 * k;
        float4 gg = gv[i4], bb = bv[i4];
        float o0 = v[k].x * rs * gg.x + bb.x;
        float o1 = v[k].y * rs * gg.y + bb.y;
        float o2 = v[k].z * rs * gg.z + bb.z;
        float o3 = v[k].w * rs * gg.w + bb.w;
        hp[i4] = make_uint2(pack_f16x2(o0, o1), pack_f16x2(o2, o3));
    }
}

// ---------------- fused prep: wcast x3 + LN1 in one launch -------------------
#define WQ_NB  ((D3_ / 32) * (D_ / 32))    /* 1728 */
#define W1_NB  ((DFF_ / 32) * (D_ / 32))   /* 2304 */
#define W2_NB  ((D_ / 32) * (DFF_ / 32))   /* 2304 */
#define LN_NB  (NTOK / 8)                  /* 1024 */
#define PREP_NB (WQ_NB + W1_NB + W2_NB + LN_NB)  /* 7360 */

__global__ void __launch_bounds__(256) prep_kernel(
    const float* __restrict__ w_qkv, const float* __restrict__ w1,
    const float* __restrict__ w2,
    const float* __restrict__ x, const float* __restrict__ ln1_g,
    const float* __restrict__ ln1_b,
    __half* __restrict__ wq, __half* __restrict__ w1t,
    __half* __restrict__ w2t, __half* __restrict__ h)
{
    int bid = blockIdx.x;
    if (bid < WQ_NB) {
        wcast_body(w_qkv, wq, D_, D3_, bid % (D3_ / 32), bid / (D3_ / 32));
        return;
    }
    bid -= WQ_NB;
    if (bid < W1_NB) {
        wcast_body(w1, w1t, D_, DFF_, bid % (DFF_ / 32), bid / (DFF_ / 32));
        return;
    }
    bid -= W1_NB;
    if (bid < W2_NB) {
        wcast_body(w2, w2t, DFF_, D_, bid % (D_ / 32), bid / (D_ / 32));
        return;
    }
    bid -= W2_NB;
    ln_body(x, ln1_g, ln1_b, h, bid);
}

// ---------------- standalone LN (for LN2) ------------------------------------
__global__ void __launch_bounds__(256) ln_f16_kernel(
    const float* __restrict__ x, const float* __restrict__ g,
    const float* __restrict__ b, __half* __restrict__ out)
{
    ln_body(x, g, b, out, blockIdx.x);
}

// ---------------- MMA GEMM: C[M,N] = A[M,K] @ B[N,K]^T, fp16 single-pass ----
// 128x128 tile, K chunk 64, 256 threads, 8 warps (4m x 2n), warp 32x64.
// cp.async 2-stage, 2 CTAs/SM.
// EPI: 1 bias+GELU->fp16 ; 2 bias,*0.9+res->fp32 ; 3 bias->fp16
#define BM   128
#define BN   128
#define BKC  64
#define ROWB 144          /* 64 fp16 = 128B + 16B pad */
#define TILEB (128 * ROWB)     /* 18432 */
#define STAGEB (2 * TILEB)     /* 36864 */
#define GEMM_SMEM (2 * STAGEB) /* 73728 */

template <int EPI>
__global__ void __launch_bounds__(256, 2) gemm_mma(
    const __half* __restrict__ A_g, const __half* __restrict__ B_g,
    const float* __restrict__ bias, const float* __restrict__ res,
    float* __restrict__ Cf, __half* __restrict__ Ch,
    int M, int N, int K)
{
    extern __shared__ char dsm[];
    const uint32_t sbase = smem_u32(dsm);

    const int tid  = threadIdx.x;
    const int lane = tid & 31;
    const int wid  = tid >> 5;
    const int wm   = wid & 3;
    const int wn   = wid >> 2;
    const int m0   = blockIdx.y * BM;
    const int n0   = blockIdx.x * BN;

    const int a_row = lane & 15;
    const int a_col = (lane >> 4) << 3;
    const uint32_t offA = (uint32_t)((wm * 32 + a_row) * ROWB + a_col * 2);
    const int b_row = (lane & 7) | ((lane >> 4) << 3);
    const int b_col = ((lane >> 3) & 1) << 3;
    const uint32_t offB = (uint32_t)(TILEB + (wn * 64 + b_row) * ROWB + b_col * 2);

    float acc[2][8][4];
    #pragma unroll
    for (int i = 0; i < 2; i++)
        #pragma unroll
        for (int j = 0; j < 8; j++)
            #pragma unroll
            for (int k = 0; k < 4; k++) acc[i][j][k] = 0.f;

    const int ldu = K >> 3;
    const uint4* ga = (const uint4*)A_g;
    const uint4* gb = (const uint4*)B_g;

    const int nchunks = K / BKC;

    auto issue = [&](int stage, int ch) {
        const int k0u = ch * (BKC / 8);
        const uint32_t so = sbase + (uint32_t)stage * STAGEB;
        #pragma unroll
        for (int i = 0; i < 4; i++) {
            const int idx = tid + i * 256;
            const int r = idx >> 3, q = idx & 7;
            const uint32_t d = so + (uint32_t)(r * ROWB + q * 16);
            cp_async16(d,         ga + (size_t)(m0 + r) * ldu + k0u + q);
            cp_async16(d + TILEB, gb + (size_t)(n0 + r) * ldu + k0u + q);
        }
    };

    issue(0, 0);
    CP_COMMIT();

    for (int ch = 0; ch < nchunks; ch++) {
        if (ch + 1 < nchunks) {
            issue((ch + 1) & 1, ch + 1);
            CP_COMMIT();
            CP_WAIT(1);
        } else {
            CP_WAIT(0);
        }
        __syncthreads();

        const uint32_t st = sbase + (uint32_t)(ch & 1) * STAGEB;
        const uint32_t aT = st + offA;
        const uint32_t bT = st + offB;

        #pragma unroll
        for (int ks = 0; ks < BKC; ks += 16) {
            uint32_t ah[2][4];
            #pragma unroll
            for (int mt = 0; mt < 2; mt++)
                ldsm_x4(ah[mt], aT + mt * (16 * ROWB) + ks * 2);
            #pragma unroll
            for (int np = 0; np < 4; np++) {
                uint32_t bh[4];
                ldsm_x4(bh, bT + np * (16 * ROWB) + ks * 2);
                #pragma unroll
                for (int mt = 0; mt < 2; mt++) {
                    mma16816(acc[mt][2 * np],     ah[mt], bh[0], bh[1]);
                    mma16816(acc[mt][2 * np + 1], ah[mt], bh[2], bh[3]);
                }
            }
        }
        __syncthreads();
    }

    // epilogue
    const int lr = lane >> 2;
    const int lc = (lane & 3) * 2;
    #pragma unroll
    for (int mt = 0; mt < 2; mt++) {
        #pragma unroll
        for (int nt = 0; nt < 8; nt++) {
            #pragma unroll
            for (int hh = 0; hh < 2; hh++) {
                const int gr = m0 + wm * 32 + mt * 16 + lr + hh * 8;
                const int gc = n0 + wn * 64 + nt * 8 + lc;
                float v0 = acc[mt][nt][hh * 2 + 0] + bias[gc];
                float v1 = acc[mt][nt][hh * 2 + 1] + bias[gc + 1];
                const size_t go = (size_t)gr * N + gc;
                if (EPI == 1) {
                    v0 = gelu_fast(v0);
                    v1 = gelu_fast(v1);
                    ((uint32_t*)Ch)[go >> 1] = pack_f16x2(v0, v1);
                } else if (EPI == 2) {
                    float2 rr = *(const float2*)&res[go];
                    float2 o2 = make_float2(v0 * SURV_ + rr.x, v1 * SURV_ + rr.y);
                    *(float2*)&Cf[go] = o2;
                } else {  // EPI == 3
                    ((uint32_t*)Ch)[go >> 1] = pack_f16x2(v0, v1);
                }
            }
        }
    }
}

// ---------------- Flash attention (champion + occupancy pin + FMA packs) -----
#define FQT 64
#define KT  64
#define QB_  9216                  /* 64 rows * 144B */
#define KB_  9216
#define FLASH_SMEM (QB_ + 4 * KB_) /* 46080 */

__global__ void __launch_bounds__(128, 4) flash_mma(
    const __half* __restrict__ qkv, const float* __restrict__ x,
    float* __restrict__ x1)
{
    extern __shared__ char fsm[];
    const uint32_t sb = smem_u32(fsm);

    const int t = threadIdx.x;
    const int lane = t & 31, wid = t >> 5;
    const int qt = blockIdx.x, h = blockIdx.y, b = blockIdx.z;
    const size_t base = (size_t)b * P_ * D3_;
    const int q0 = qt * FQT, hc = h * 64;

    #pragma unroll
    for (int i = 0; i < 4; i++) {
        int idx = t + i * 128;
        int r = idx >> 3, c8 = (idx & 7) << 3;
        *(uint4*)(fsm + r * 144 + c8 * 2) =
            *(const uint4*)(qkv + base + (size_t)(q0 + r) * D3_ + hc + c8);
    }

    auto issueKV = [&](int stage, int kt) {
        const int k0 = kt * KT;
        const uint32_t kb = sb + QB_ + (uint32_t)stage * KB_;
        const uint32_t vb = sb + QB_ + 2 * KB_ + (uint32_t)stage * KB_;
        #pragma unroll
        for (int i = 0; i < 4; i++) {
            int idx = t + i * 128;
            int r = idx >> 3, c8 = (idx & 7) << 3;
            cp_async16(kb + r * 144 + c8 * 2,
                       qkv + base + (size_t)(k0 + r) * D3_ + D_ + hc + c8);
            cp_async16(vb + r * 144 + c8 * 2,
                       qkv + base + (size_t)(k0 + r) * D3_ + 2 * D_ + hc + c8);
        }
    };

    issueKV(0, 0);
    CP_COMMIT();
    __syncthreads();

    uint32_t qf[4][4];
    {
        const int qr = lane & 15;
        const int qc = (lane >> 4) << 3;
        #pragma unroll
        for (int ks = 0; ks < 4; ks++)
            ldsm_x4(qf[ks], sb + (wid * 16 + qr) * 144 + (ks * 16 + qc) * 2);
    }

    float mrow[2] = {-1e30f, -1e30f};
    float lrow[2] = {0.f, 0.f};
    float o[8][4];
    #pragma unroll
    for (int i = 0; i < 8; i++)
        #pragma unroll
        for (int j = 0; j < 4; j++) o[i][j] = 0.f;

    const float SCL = 0.18033688011112042f;  // (1/8) * log2(e)

    const int krow = (lane & 7) + ((lane >> 4) << 3);
    const int kcol = ((lane >> 3) & 1) << 3;
    const int vrow = (lane & 7) + (((lane >> 3) & 1) << 3);
    const int vcol = (lane >> 4) << 3;

    const int niter = P_ / KT;
    for (int kt = 0; kt < niter; kt++) {
        if (kt + 1 < niter) {
            issueKV((kt + 1) & 1, kt + 1);
            CP_COMMIT();
            CP_WAIT(1);
        } else {
            CP_WAIT(0);
        }
        __syncthreads();

        const uint32_t kst = sb + QB_ + (uint32_t)(kt & 1) * KB_;
        const uint32_t vst = sb + QB_ + 2 * KB_ + (uint32_t)(kt & 1) * KB_;

        float s[8][4];
        #pragma unroll
        for (int i = 0; i < 8; i++)
            #pragma unroll
            for (int j = 0; j < 4; j++) s[i][j] = 0.f;
        #pragma unroll
        for (int ks = 0; ks < 4; ks++) {
            #pragma unroll
            for (int tp = 0; tp < 4; tp++) {
                uint32_t kf[4];
                ldsm_x4(kf, kst + (tp * 16 + krow) * 144 + (ks * 16 + kcol) * 2);
                mma16816(s[2 * tp],     qf[ks], kf[0], kf[1]);
                mma16816(s[2 * tp + 1], qf[ks], kf[2], kf[3]);
            }
        }

        float pm0 = -1e30f, pm1 = -1e30f;
        #pragma unroll
        for (int nt = 0; nt < 8; nt++) {
            pm0 = fmaxf(pm0, fmaxf(s[nt][0], s[nt][1]));
            pm1 = fmaxf(pm1, fmaxf(s[nt][2], s[nt][3]));
        }
        pm0 = fmaxf(pm0, __shfl_xor_sync(0xffffffffu, pm0, 1));
        pm0 = fmaxf(pm0, __shfl_xor_sync(0xffffffffu, pm0, 2));
        pm1 = fmaxf(pm1, __shfl_xor_sync(0xffffffffu, pm1, 1));
        pm1 = fmaxf(pm1, __shfl_xor_sync(0xffffffffu, pm1, 2));
        const float mn0 = fmaxf(mrow[0], pm0);
        const float mn1 = fmaxf(mrow[1], pm1);
        const float f0 = ex2f((mrow[0] - mn0) * SCL);
        const float f1 = ex2f((mrow[1] - mn1) * SCL);
        const float c0 = -mn0 * SCL;           // pack operand = s*SCL + c (1 FMA)
        const float c1 = -mn1 * SCL;

        uint32_t pf[4][4];
        #pragma unroll
        for (int ks = 0; ks < 4; ks++) {
            pf[ks][0] = h2ex2(pack_f16x2(fmaf(s[2 * ks][0], SCL, c0),
                                         fmaf(s[2 * ks][1], SCL, c0)));
            pf[ks][1] = h2ex2(pack_f16x2(fmaf(s[2 * ks][2], SCL, c1),
                                         fmaf(s[2 * ks][3], SCL, c1)));
            pf[ks][2] = h2ex2(pack_f16x2(fmaf(s[2 * ks + 1][0], SCL, c0),
                                         fmaf(s[2 * ks + 1][1], SCL, c0)));
            pf[ks][3] = h2ex2(pack_f16x2(fmaf(s[2 * ks + 1][2], SCL, c1),
                                         fmaf(s[2 * ks + 1][3], SCL, c1)));
        }

        // row sums via ones-MMA (la[0]=row lr, la[2]=row lr+8)
        float la[4] = {0.f, 0.f, 0.f, 0.f};
        #pragma unroll
        for (int ks = 0; ks < 4; ks++)
            mma16816(la, pf[ks], ONES2, ONES2);

        lrow[0] = lrow[0] * f0 + la[0];
        lrow[1] = lrow[1] * f1 + la[2];
        mrow[0] = mn0;
        mrow[1] = mn1;

        #pragma unroll
        for (int nt = 0; nt < 8; nt++) {
            o[nt][0] *= f0; o[nt][1] *= f0;
            o[nt][2] *= f1; o[nt][3] *= f1;
        }

        #pragma unroll
        for (int ks = 0; ks < 4; ks++) {
            #pragma unroll
            for (int tp = 0; tp < 4; tp++) {
                uint32_t vf[4];
                ldsm_x4_t(vf, vst + (ks * 16 + vrow) * 144 + (tp * 16 + vcol) * 2);
                mma16816(o[2 * tp],     pf[ks], vf[0], vf[1]);
                mma16816(o[2 * tp + 1], pf[ks], vf[2], vf[3]);
            }
        }
        __syncthreads();
    }

    const float inv0 = 1.0f / lrow[0];
    const float inv1 = 1.0f / lrow[1];
    const int r0 = q0 + wid * 16 + (lane >> 2);
    const size_t row0 = ((size_t)b * P_ + r0) * D_ + hc + (lane & 3) * 2;
    const size_t row1 = row0 + 8 * D_;
    #pragma unroll
    for (int nt = 0; nt < 8; nt++) {
        float2 xa = *(const float2*)&x[row0 + nt * 8];
        float2 ra;
        ra.x = o[nt][0] * inv0 * SURV_ + xa.x;
        ra.y = o[nt][1] * inv0 * SURV_ + xa.y;
        *(float2*)&x1[row0 + nt * 8] = ra;
        float2 xb = *(const float2*)&x[row1 + nt * 8];
        float2 rb;
        rb.x = o[nt][2] * inv1 * SURV_ + xb.x;
        rb.y = o[nt][3] * inv1 * SURV_ + xb.y;
        *(float2*)&x1[row1 + nt * 8] = rb;
    }
}

// ---------------- launch ----------------------------------------------------
extern "C" void kernel_launch(void* const* d_in, const int* in_sizes, int n_in,
                              void* d_out, int out_size)
{
    const float* x     = (const float*)d_in[0];
    const float* ln1_g = (const float*)d_in[1];
    const float* ln1_b = (const float*)d_in[2];
    const float* w_qkv = (const float*)d_in[3];
    const float* b_qkv = (const float*)d_in[4];
    const float* ln2_g = (const float*)d_in[5];
    const float* ln2_b = (const float*)d_in[6];
    const float* w1    = (const float*)d_in[7];
    const float* b1    = (const float*)d_in[8];
    const float* w2    = (const float*)d_in[9];
    const float* b2    = (const float*)d_in[10];
    float* out = (float*)d_out;

    __half *h, *qkvh, *ffn, *wq, *w1t, *w2t;
    float *x1;
    cudaGetSymbolAddress((void**)&h,    g_h);
    cudaGetSymbolAddress((void**)&qkvh, g_qkvh);
    cudaGetSymbolAddress((void**)&x1,   g_x1);
    cudaGetSymbolAddress((void**)&ffn,  g_ffn);
    cudaGetSymbolAddress((void**)&wq,   g_wq);
    cudaGetSymbolAddress((void**)&w1t,  g_w1);
    cudaGetSymbolAddress((void**)&w2t,  g_w2);

    cudaFuncSetAttribute(gemm_mma<1>,
                         cudaFuncAttributeMaxDynamicSharedMemorySize, GEMM_SMEM);
    cudaFuncSetAttribute(gemm_mma<2>,
                         cudaFuncAttributeMaxDynamicSharedMemorySize, GEMM_SMEM);
    cudaFuncSetAttribute(gemm_mma<3>,
                         cudaFuncAttributeMaxDynamicSharedMemorySize, GEMM_SMEM);
    cudaFuncSetAttribute(flash_mma,
                         cudaFuncAttributeMaxDynamicSharedMemorySize, FLASH_SMEM);

    // 0) fused prep: weight transpose+cast x3 + LN1, one launch
    prep_kernel<<<PREP_NB, 256>>>(w_qkv, w1, w2, x, ln1_g, ln1_b,
                                  wq, w1t, w2t, h);
    // 1) QKV projection -> fp16
    gemm_mma<3><<<dim3(D3_ / BN, NTOK / BM), 256, GEMM_SMEM>>>(
        h, wq, b_qkv, nullptr, nullptr, qkvh, NTOK, D3_, D_);
    // 2) attention + residual -> x1
    flash_mma<<<dim3(P_ / FQT, H_, B_), 128, FLASH_SMEM>>>(qkvh, x, x1);
    // 3) LN2 -> fp16
    ln_f16_kernel<<<NTOK / 8, 256>>>(x1, ln2_g, ln2_b, h);
    // 4) MLP up + GELU -> fp16
    gemm_mma<1><<<dim3(DFF_ / BN, NTOK / BM), 256, GEMM_SMEM>>>(
        h, w1t, b1, nullptr, nullptr, ffn, NTOK, DFF_, D_);
    // 5) MLP down + droppath + residual -> out
    gemm_mma<2><<<dim3(D_ / BN, NTOK / BM), 256, GEMM_SMEM>>>(
        ffn, w2t, b2, x1, out, nullptr, NTOK, D_, DFF_);
}